// round 5
// baseline (speedup 1.0000x reference)
#include <cuda_runtime.h>
#include <cuda_bf16.h>
#include <math.h>
#include <stdint.h>

// ---------------- problem constants (fixed by the dataset) ----------------
#define NN   50000      // nodes
#define EE   500000     // edges
#define GG   50         // graphs
#define INF_ 3.402823466e+38f

#define H1D  64         // HID[0]
#define H2D  128        // HID[1]
#define NH   4          // heads
#define SLOPE 0.2f

// ---------------- scratch (device globals; no allocation) ----------------
__device__ float g_fs1[NN * NH * H1D];
__device__ float g_fd1[NN * NH * H1D];
__device__ float g_fs2[NN * NH * H2D];
__device__ float g_fd2[NN * NH * H2D];
__device__ float g_h2 [NN * H2D];

__device__ __nv_bfloat16 g_xh[NN * 128];   // x split
__device__ __nv_bfloat16 g_xl[NN * 128];
__device__ __nv_bfloat16 g_h1h[NN * H1D];  // h1 split (written by GAT-1 epilogue)
__device__ __nv_bfloat16 g_h1l[NN * H1D];
__device__ uint32_t g_wb[8][16384];        // weight splits, k-paired words

__device__ int g_deg[NN];
__device__ int g_rs [NN + 1];
__device__ int g_cur[NN];
__device__ int g_adj[EE];       // dst-sorted src list (CSR payload)

// ---------------- split converters ----------------
__global__ void k_split_f32(const float* __restrict__ src,
                            __nv_bfloat16* __restrict__ hi, __nv_bfloat16* __restrict__ lo, int n) {
    int i = blockIdx.x * blockDim.x + threadIdx.x;
    if (i < n) {
        float v = src[i];
        __nv_bfloat16 h = __float2bfloat16_rn(v);
        hi[i] = h;
        lo[i] = __float2bfloat16_rn(v - __bfloat162float(h));
    }
}

// W [K][M] fp32 -> paired words: out[k2*M + n] = pack(bf16(W[2k2][n]), bf16(W[2k2+1][n]))
__global__ void k_split_w(const float* __restrict__ W,
                          uint32_t* __restrict__ outh, uint32_t* __restrict__ outl,
                          int K2, int M) {
    int i = blockIdx.x * blockDim.x + threadIdx.x;
    if (i >= K2 * M) return;
    int k2 = i / M, n = i - k2 * M;
    float e0 = W[(2 * k2) * M + n];
    float e1 = W[(2 * k2 + 1) * M + n];
    __nv_bfloat16 h0 = __float2bfloat16_rn(e0);
    __nv_bfloat16 h1 = __float2bfloat16_rn(e1);
    __nv_bfloat16 l0 = __float2bfloat16_rn(e0 - __bfloat162float(h0));
    __nv_bfloat16 l1 = __float2bfloat16_rn(e1 - __bfloat162float(h1));
    uint32_t wh = (uint32_t)__bfloat16_as_ushort(h0) | ((uint32_t)__bfloat16_as_ushort(h1) << 16);
    uint32_t wl = (uint32_t)__bfloat16_as_ushort(l0) | ((uint32_t)__bfloat16_as_ushort(l1) << 16);
    outh[i] = wh;
    outl[i] = wl;
}

// ---------------- CSR build ----------------
__global__ void k_hist(const int* __restrict__ dst, int E) {
    int i = blockIdx.x * blockDim.x + threadIdx.x;
    if (i < E) atomicAdd(&g_deg[dst[i]], 1);
}

__global__ void k_scan(int E) {
    __shared__ int sm[1024];
    int tid = threadIdx.x;
    const int chunk = (NN + 1023) / 1024;
    int b = tid * chunk;
    int e = b + chunk; if (e > NN) e = NN;
    int s = 0;
    for (int i = b; i < e; i++) s += g_deg[i];
    sm[tid] = s;
    __syncthreads();
    for (int off = 1; off < 1024; off <<= 1) {
        int v = (tid >= off) ? sm[tid - off] : 0;
        __syncthreads();
        sm[tid] += v;
        __syncthreads();
    }
    int run = sm[tid] - s;   // exclusive prefix for this chunk
    for (int i = b; i < e; i++) {
        g_rs[i] = run;
        g_cur[i] = run;
        run += g_deg[i];
    }
    if (tid == 0) g_rs[NN] = E;
}

__global__ void k_scatter(const int* __restrict__ dst, int E) {
    int i = blockIdx.x * blockDim.x + threadIdx.x;
    if (i < E) {
        int p = atomicAdd(&g_cur[dst[i]], 1);
        g_adj[p] = i;
    }
}

__global__ void k_sortseg() {        // per-node insertion sort -> deterministic order
    int v = blockIdx.x * blockDim.x + threadIdx.x;
    if (v >= NN) return;
    int s = g_rs[v], e = g_rs[v + 1];
    for (int i = s + 1; i < e; i++) {
        int key = g_adj[i];
        int j = i - 1;
        while (j >= s && g_adj[j] > key) { g_adj[j + 1] = g_adj[j]; j--; }
        g_adj[j + 1] = key;
    }
}

__global__ void k_eid2src(const int* __restrict__ src, int E) {
    int i = blockIdx.x * blockDim.x + threadIdx.x;
    if (i < E) g_adj[i] = src[g_adj[i]];
}

// ---------------- bf16 mma helper ----------------
__device__ __forceinline__ void mma_bf16(float c[4], const uint32_t a[4], uint32_t b0, uint32_t b1) {
    asm("mma.sync.aligned.m16n8k16.row.col.f32.bf16.bf16.f32 "
        "{%0,%1,%2,%3}, {%4,%5,%6,%7}, {%8,%9}, {%0,%1,%2,%3};"
        : "+f"(c[0]), "+f"(c[1]), "+f"(c[2]), "+f"(c[3])
        : "r"(a[0]), "r"(a[1]), "r"(a[2]), "r"(a[3]), "r"(b0), "r"(b1));
}

// ---------------- dual-output bf16x3 tensor GEMM + bias ----------------
// C = A @ B + bias with A = Ah+Al (bf16 split, row-major), B pre-split k-paired words.
// 3 passes: Ah*Bh + Al*Bh + Ah*Bl (~1e-5 rel accuracy). Block 128x128, BK=32,
// 256 threads (8 warps: 4x2 of 32x64 warp tiles). Pure LDS+MMA inner loop.
__global__ __launch_bounds__(256)
void k_gemm_bf16x3_dual(const __nv_bfloat16* __restrict__ Agh, const __nv_bfloat16* __restrict__ Agl,
                        const uint32_t* __restrict__ B1h, const uint32_t* __restrict__ B1l,
                        const float* __restrict__ b1, float* __restrict__ C1,
                        const uint32_t* __restrict__ B2h, const uint32_t* __restrict__ B2l,
                        const float* __restrict__ b2, float* __restrict__ C2,
                        int Nrows, int K, int M) {
    const int nbx = M >> 7;
    int bx = blockIdx.x;
    const uint32_t* Bh = B1h; const uint32_t* Bl = B1l;
    const float* bias = b1; float* C = C1;
    if (bx >= nbx) { bx -= nbx; Bh = B2h; Bl = B2l; bias = b2; C = C2; }
    const int row0 = blockIdx.y << 7;
    const int col0 = bx << 7;
    const int K2 = K >> 1;                 // words per A row

    __shared__ uint32_t sA[2][128][20];    // [split][m][k2-word], pad 20 -> conflict-free
    __shared__ uint32_t sB[2][16][136];    // [split][k2-word][n], pad 136 -> conflict-free

    const int tid = threadIdx.x;
    const int lane = tid & 31;
    const int wid = tid >> 5;
    const int wm = wid & 3;                // 0..3 -> 32 rows
    const int wn = wid >> 2;               // 0..1 -> 64 cols
    const int g = lane >> 2;               // 0..7
    const int t = lane & 3;                // 0..3

    const uint32_t* Ahw = (const uint32_t*)Agh;
    const uint32_t* Alw = (const uint32_t*)Agl;

    float acc[2][8][4];
#pragma unroll
    for (int i = 0; i < 2; i++)
#pragma unroll
        for (int j = 0; j < 8; j++)
#pragma unroll
            for (int q = 0; q < 4; q++) acc[i][j][q] = 0.f;

    const int ktiles = K >> 5;
    for (int kt = 0; kt < ktiles; kt++) {
        const int kk2 = kt << 4;
        // A tile: 128 rows x 16 words per split; 512 uint4 per split
#pragma unroll
        for (int i = 0; i < 2; i++) {
            int f = tid + i * 256;
            int r = f >> 2;
            int c4 = (f & 3) * 4;
            uint4 vh = make_uint4(0u, 0u, 0u, 0u), vl = make_uint4(0u, 0u, 0u, 0u);
            if (row0 + r < Nrows) {
                long w = (long)(row0 + r) * K2 + kk2 + c4;
                vh = *(const uint4*)(Ahw + w);
                vl = *(const uint4*)(Alw + w);
            }
            *(uint4*)&sA[0][r][c4] = vh;
            *(uint4*)&sA[1][r][c4] = vl;
        }
        // B tile: 16 k2-rows x 128 words per split
#pragma unroll
        for (int i = 0; i < 2; i++) {
            int f = tid + i * 256;
            int r = f >> 5;
            int c4 = (f & 31) * 4;
            long w = (long)(kk2 + r) * M + col0 + c4;
            *(uint4*)&sB[0][r][c4] = *(const uint4*)(Bh + w);
            *(uint4*)&sB[1][r][c4] = *(const uint4*)(Bl + w);
        }
        __syncthreads();

#pragma unroll
        for (int k16 = 0; k16 < 2; k16++) {
            const int kb = k16 * 8;
            uint32_t af[2][2][4];   // [split][mt][frag]
#pragma unroll
            for (int s = 0; s < 2; s++)
#pragma unroll
                for (int mt = 0; mt < 2; mt++) {
                    const int mr = wm * 32 + mt * 16;
                    af[s][mt][0] = sA[s][mr + g][kb + t];
                    af[s][mt][1] = sA[s][mr + 8 + g][kb + t];
                    af[s][mt][2] = sA[s][mr + g][kb + 4 + t];
                    af[s][mt][3] = sA[s][mr + 8 + g][kb + 4 + t];
                }
#pragma unroll
            for (int nt = 0; nt < 8; nt++) {
                const int nc = wn * 64 + nt * 8 + g;
                uint32_t bh0 = sB[0][kb + t][nc];
                uint32_t bh1 = sB[0][kb + 4 + t][nc];
                uint32_t bl0 = sB[1][kb + t][nc];
                uint32_t bl1 = sB[1][kb + 4 + t][nc];
#pragma unroll
                for (int mt = 0; mt < 2; mt++) {
                    mma_bf16(acc[mt][nt], af[0][mt], bh0, bh1);
                    mma_bf16(acc[mt][nt], af[1][mt], bh0, bh1);
                    mma_bf16(acc[mt][nt], af[0][mt], bl0, bl1);
                }
            }
        }
        __syncthreads();
    }

    // epilogue: bias + guarded float2 stores (m16n8 C layout)
#pragma unroll
    for (int nt = 0; nt < 8; nt++) {
        const int c = col0 + wn * 64 + nt * 8 + t * 2;
        const float2 bv = *(const float2*)(bias + c);
#pragma unroll
        for (int mt = 0; mt < 2; mt++) {
            const int r0 = row0 + wm * 32 + mt * 16 + g;
            if (r0 < Nrows) {
                float2 o; o.x = acc[mt][nt][0] + bv.x; o.y = acc[mt][nt][1] + bv.y;
                *(float2*)(C + (long)r0 * M + c) = o;
            }
            if (r0 + 8 < Nrows) {
                float2 o; o.x = acc[mt][nt][2] + bv.x; o.y = acc[mt][nt][3] + bv.y;
                *(float2*)(C + (long)(r0 + 8) * M + c) = o;
            }
        }
    }
}

// ---------------- fused GATv2 edge-softmax + aggregate + head-maxpool ----------------
// block = 128 threads = 4 warps = 4 heads; grid-stride over nodes.
// SPLIT: write result as bf16 hi/lo (feeds next GEMM); else fp32.
template <int D, bool SPLIT>
__global__ void k_gat(const float* __restrict__ fs, const float* __restrict__ fd,
                      const float* __restrict__ attn, float* __restrict__ hout,
                      __nv_bfloat16* __restrict__ hh, __nv_bfloat16* __restrict__ hl) {
    constexpr int VPT = D / 32;
    constexpr int HD = NH * D;
    __shared__ float sh[NH][D];
    const int lane = threadIdx.x & 31;
    const int h = threadIdx.x >> 5;

    float areg[VPT];
#pragma unroll
    for (int i = 0; i < VPT; i++) areg[i] = attn[h * D + i * 32 + lane];

    for (int v = blockIdx.x; v < NN; v += gridDim.x) {
        float fdr[VPT];
        const float* fdp = fd + (long)v * HD + h * D;
#pragma unroll
        for (int i = 0; i < VPT; i++) fdr[i] = fdp[i * 32 + lane];

        const int s0 = g_rs[v], s1 = g_rs[v + 1];
        float m = -INF_, ssum = 0.f;
        float acc[VPT];
#pragma unroll
        for (int i = 0; i < VPT; i++) acc[i] = 0.f;

        int u = (s0 < s1) ? g_adj[s0] : 0;
        for (int idx = s0; idx < s1; idx++) {
            int unext = (idx + 1 < s1) ? g_adj[idx + 1] : 0;
            const float* fsp = fs + (long)u * HD + h * D;
            float fu[VPT];
            float p = 0.f;
#pragma unroll
            for (int i = 0; i < VPT; i++) {
                fu[i] = fsp[i * 32 + lane];
                float t = fu[i] + fdr[i];
                t = t > 0.f ? t : SLOPE * t;
                p += areg[i] * t;
            }
#pragma unroll
            for (int o = 16; o; o >>= 1) p += __shfl_xor_sync(0xffffffffu, p, o);
            if (p <= m) {                      // warp-uniform branch (p uniform after reduce)
                float pe = __expf(p - m);
                ssum += pe;
#pragma unroll
                for (int i = 0; i < VPT; i++) acc[i] += pe * fu[i];
            } else {
                float sc = __expf(m - p);      // first iter: exp(-inf) = 0
                ssum = ssum * sc + 1.f;
#pragma unroll
                for (int i = 0; i < VPT; i++) acc[i] = acc[i] * sc + fu[i];
                m = p;
            }
            u = unext;
        }
        float inv = (s1 > s0) ? 1.f / ssum : 0.f;
#pragma unroll
        for (int i = 0; i < VPT; i++) sh[h][i * 32 + lane] = acc[i] * inv;
        __syncthreads();
        for (int d = threadIdx.x; d < D; d += blockDim.x) {
            float mx = fmaxf(fmaxf(sh[0][d], sh[1][d]), fmaxf(sh[2][d], sh[3][d]));
            if (SPLIT) {
                __nv_bfloat16 hi = __float2bfloat16_rn(mx);
                hh[(long)v * D + d] = hi;
                hl[(long)v * D + d] = __float2bfloat16_rn(mx - __bfloat162float(hi));
            } else {
                hout[(long)v * D + d] = mx;
            }
        }
        __syncthreads();
    }
}

// ---------------- global attention pooling: one block (128 thr) per graph ----------------
__global__ void k_pool(const float* __restrict__ gw, const float* __restrict__ gb,
                       float* __restrict__ out, int npg) {
    const int g = blockIdx.x;
    const int tid = threadIdx.x;
    const int lane = tid & 31;
    const int w = tid >> 5;
    extern __shared__ float sg[];
    __shared__ float red[16];
    const int base = g * npg;

    float gwr[4];
#pragma unroll
    for (int i = 0; i < 4; i++) gwr[i] = gw[i * 32 + lane];
    const float gbv = gb[0];

    for (int v = w; v < npg; v += 4) {
        const float* hp = g_h2 + (long)(base + v) * H2D;
        float p = 0.f;
#pragma unroll
        for (int i = 0; i < 4; i++) p += gwr[i] * hp[i * 32 + lane];
#pragma unroll
        for (int o = 16; o; o >>= 1) p += __shfl_xor_sync(0xffffffffu, p, o);
        if (lane == 0) sg[v] = p + gbv;
    }
    __syncthreads();

    float mx = -INF_;
    for (int v = tid; v < npg; v += 128) mx = fmaxf(mx, sg[v]);
#pragma unroll
    for (int o = 16; o; o >>= 1) mx = fmaxf(mx, __shfl_xor_sync(0xffffffffu, mx, o));
    if (lane == 0) red[w] = mx;
    __syncthreads();
    if (tid == 0) red[8] = fmaxf(fmaxf(red[0], red[1]), fmaxf(red[2], red[3]));
    __syncthreads();
    const float M = red[8];

    float ss = 0.f;
    for (int v = tid; v < npg; v += 128) {
        float e = __expf(sg[v] - M);
        sg[v] = e;
        ss += e;
    }
#pragma unroll
    for (int o = 16; o; o >>= 1) ss += __shfl_xor_sync(0xffffffffu, ss, o);
    if (lane == 0) red[w] = ss;
    __syncthreads();
    if (tid == 0) red[9] = red[0] + red[1] + red[2] + red[3];
    __syncthreads();
    const float inv = 1.f / red[9];

    float accD = 0.f;
    for (int v = 0; v < npg; v++)
        accD += sg[v] * g_h2[(long)(base + v) * H2D + tid];
    out[g * H2D + tid] = accD * inv;
}

// ---------------- launch ----------------
extern "C" void kernel_launch(void* const* d_in, const int* in_sizes, int n_in,
                              void* d_out, int out_size) {
    const float* x    = (const float*)d_in[0];
    const int* esrc   = (const int*)d_in[1];
    const int* edst   = (const int*)d_in[2];
    // d_in[3] = node_graph (contiguous blocks; unused)
    const float* Wl1  = (const float*)d_in[4];
    const float* bl1  = (const float*)d_in[5];
    const float* Wr1  = (const float*)d_in[6];
    const float* br1  = (const float*)d_in[7];
    const float* at1  = (const float*)d_in[8];
    const float* Wl2  = (const float*)d_in[9];
    const float* bl2  = (const float*)d_in[10];
    const float* Wr2  = (const float*)d_in[11];
    const float* br2  = (const float*)d_in[12];
    const float* at2  = (const float*)d_in[13];
    const float* gw   = (const float*)d_in[14];
    const float* gb   = (const float*)d_in[15];

    const int E = in_sizes[1];
    const int N = in_sizes[0] / 128;
    const int G = out_size / H2D;
    const int npg = N / G;

    float *fs1, *fd1, *fs2, *fd2, *h2;
    __nv_bfloat16 *xh, *xl, *h1h, *h1l;
    uint32_t* wb;
    int* degp;
    cudaGetSymbolAddress((void**)&fs1, g_fs1);
    cudaGetSymbolAddress((void**)&fd1, g_fd1);
    cudaGetSymbolAddress((void**)&fs2, g_fs2);
    cudaGetSymbolAddress((void**)&fd2, g_fd2);
    cudaGetSymbolAddress((void**)&h2,  g_h2);
    cudaGetSymbolAddress((void**)&xh,  g_xh);
    cudaGetSymbolAddress((void**)&xl,  g_xl);
    cudaGetSymbolAddress((void**)&h1h, g_h1h);
    cudaGetSymbolAddress((void**)&h1l, g_h1l);
    cudaGetSymbolAddress((void**)&wb,  g_wb);
    cudaGetSymbolAddress((void**)&degp, g_deg);

    const int rowBlocks = (N + 127) / 128;

    // 0: split x
    k_split_f32<<<(N * 128 + 255) / 256, 256>>>(x, xh, xl, N * 128);
    // 1-2: split layer-1 weights (K=128 -> K2=64, M=256)
    k_split_w<<<(64 * 256 + 255) / 256, 256>>>(Wl1, wb + 0 * 16384, wb + 1 * 16384, 64, 256);
    k_split_w<<<(64 * 256 + 255) / 256, 256>>>(Wr1, wb + 2 * 16384, wb + 3 * 16384, 64, 256);
    // 3: layer-1 dual GEMM  (the ncu-profiled launch slot)
    {
        dim3 grid(2 * (NH * H1D / 128), rowBlocks);
        k_gemm_bf16x3_dual<<<grid, 256>>>(xh, xl,
                                          wb + 0 * 16384, wb + 1 * 16384, bl1, fs1,
                                          wb + 2 * 16384, wb + 3 * 16384, br1, fd1,
                                          N, 128, NH * H1D);
    }

    // ---- CSR build (deterministic) ----
    cudaMemsetAsync(degp, 0, NN * sizeof(int));
    k_hist<<<(E + 255) / 256, 256>>>(edst, E);
    k_scan<<<1, 1024>>>(E);
    k_scatter<<<(E + 255) / 256, 256>>>(edst, E);
    k_sortseg<<<(NN + 255) / 256, 256>>>();
    k_eid2src<<<(E + 255) / 256, 256>>>(esrc, E);

    // GAT layer 1 -> split h1
    k_gat<H1D, true><<<2368, 128>>>(fs1, fd1, at1, nullptr, h1h, h1l);

    // split layer-2 weights (K=64 -> K2=32, M=512)
    k_split_w<<<(32 * 512 + 255) / 256, 256>>>(Wl2, wb + 4 * 16384, wb + 5 * 16384, 32, 512);
    k_split_w<<<(32 * 512 + 255) / 256, 256>>>(Wr2, wb + 6 * 16384, wb + 7 * 16384, 32, 512);
    // layer-2 dual GEMM
    {
        dim3 grid(2 * (NH * H2D / 128), rowBlocks);
        k_gemm_bf16x3_dual<<<grid, 256>>>(h1h, h1l,
                                          wb + 4 * 16384, wb + 5 * 16384, bl2, fs2,
                                          wb + 6 * 16384, wb + 7 * 16384, br2, fd2,
                                          N, H1D, NH * H2D);
    }
    k_gat<H2D, false><<<2368, 128>>>(fs2, fd2, at2, h2, nullptr, nullptr);

    // pooling
    k_pool<<<G, 128, npg * sizeof(float)>>>(gw, gb, (float*)d_out, npg);
}

// round 6
// speedup vs baseline: 1.0509x; 1.0509x over previous
#include <cuda_runtime.h>
#include <cuda_bf16.h>
#include <math.h>
#include <stdint.h>

// ---------------- problem constants (fixed by the dataset) ----------------
#define NN   50000      // nodes
#define EE   500000     // edges
#define GG   50         // graphs
#define INF_ 3.402823466e+38f

#define H1D  64         // HID[0]
#define H2D  128        // HID[1]
#define NH   4          // heads
#define SLOPE 0.2f

// ---------------- scratch (device globals; no allocation) ----------------
__device__ float g_fs1[NN * NH * H1D];
__device__ float g_fd1[NN * NH * H1D];
__device__ float g_fs2[NN * NH * H2D];
__device__ float g_fd2[NN * NH * H2D];
__device__ float g_h2 [NN * H2D];

__device__ __nv_bfloat16 g_xh[NN * 128];   // x split
__device__ __nv_bfloat16 g_xl[NN * 128];
__device__ __nv_bfloat16 g_h1h[NN * H1D];  // h1 split (written by GAT-1 epilogue)
__device__ __nv_bfloat16 g_h1l[NN * H1D];
__device__ uint32_t g_wb[8][16384];        // weight splits, k-paired words

__device__ int g_deg[NN];
__device__ int g_rs [NN + 1];
__device__ int g_cur[NN];
__device__ int g_adj[EE];       // dst-sorted src list (CSR payload)

// ---------------- split converters ----------------
__global__ void k_split_f32(const float* __restrict__ src,
                            __nv_bfloat16* __restrict__ hi, __nv_bfloat16* __restrict__ lo, int n) {
    int i = blockIdx.x * blockDim.x + threadIdx.x;
    if (i < n) {
        float v = src[i];
        __nv_bfloat16 h = __float2bfloat16_rn(v);
        hi[i] = h;
        lo[i] = __float2bfloat16_rn(v - __bfloat162float(h));
    }
}

// W [K][M] fp32 -> paired words: out[k2*M + n] = pack(bf16(W[2k2][n]), bf16(W[2k2+1][n]))
__global__ void k_split_w(const float* __restrict__ W,
                          uint32_t* __restrict__ outh, uint32_t* __restrict__ outl,
                          int K2, int M) {
    int i = blockIdx.x * blockDim.x + threadIdx.x;
    if (i >= K2 * M) return;
    int k2 = i / M, n = i - k2 * M;
    float e0 = W[(2 * k2) * M + n];
    float e1 = W[(2 * k2 + 1) * M + n];
    __nv_bfloat16 h0 = __float2bfloat16_rn(e0);
    __nv_bfloat16 h1 = __float2bfloat16_rn(e1);
    __nv_bfloat16 l0 = __float2bfloat16_rn(e0 - __bfloat162float(h0));
    __nv_bfloat16 l1 = __float2bfloat16_rn(e1 - __bfloat162float(h1));
    uint32_t wh = (uint32_t)__bfloat16_as_ushort(h0) | ((uint32_t)__bfloat16_as_ushort(h1) << 16);
    uint32_t wl = (uint32_t)__bfloat16_as_ushort(l0) | ((uint32_t)__bfloat16_as_ushort(l1) << 16);
    outh[i] = wh;
    outl[i] = wl;
}

// ---------------- CSR build ----------------
__global__ void k_hist(const int* __restrict__ dst, int E) {
    int i = blockIdx.x * blockDim.x + threadIdx.x;
    if (i < E) atomicAdd(&g_deg[dst[i]], 1);
}

__global__ void k_scan(int E) {
    __shared__ int sm[1024];
    int tid = threadIdx.x;
    const int chunk = (NN + 1023) / 1024;
    int b = tid * chunk;
    int e = b + chunk; if (e > NN) e = NN;
    int s = 0;
    for (int i = b; i < e; i++) s += g_deg[i];
    sm[tid] = s;
    __syncthreads();
    for (int off = 1; off < 1024; off <<= 1) {
        int v = (tid >= off) ? sm[tid - off] : 0;
        __syncthreads();
        sm[tid] += v;
        __syncthreads();
    }
    int run = sm[tid] - s;   // exclusive prefix for this chunk
    for (int i = b; i < e; i++) {
        g_rs[i] = run;
        g_cur[i] = run;
        run += g_deg[i];
    }
    if (tid == 0) g_rs[NN] = E;
}

__global__ void k_scatter(const int* __restrict__ dst, int E) {
    int i = blockIdx.x * blockDim.x + threadIdx.x;
    if (i < E) {
        int p = atomicAdd(&g_cur[dst[i]], 1);
        g_adj[p] = i;
    }
}

__global__ void k_sortseg() {        // per-node insertion sort -> deterministic order
    int v = blockIdx.x * blockDim.x + threadIdx.x;
    if (v >= NN) return;
    int s = g_rs[v], e = g_rs[v + 1];
    for (int i = s + 1; i < e; i++) {
        int key = g_adj[i];
        int j = i - 1;
        while (j >= s && g_adj[j] > key) { g_adj[j + 1] = g_adj[j]; j--; }
        g_adj[j + 1] = key;
    }
}

__global__ void k_eid2src(const int* __restrict__ src, int E) {
    int i = blockIdx.x * blockDim.x + threadIdx.x;
    if (i < E) g_adj[i] = src[g_adj[i]];
}

// ---------------- bf16 mma helper ----------------
__device__ __forceinline__ void mma_bf16(float c[4], const uint32_t a[4], uint32_t b0, uint32_t b1) {
    asm("mma.sync.aligned.m16n8k16.row.col.f32.bf16.bf16.f32 "
        "{%0,%1,%2,%3}, {%4,%5,%6,%7}, {%8,%9}, {%0,%1,%2,%3};"
        : "+f"(c[0]), "+f"(c[1]), "+f"(c[2]), "+f"(c[3])
        : "r"(a[0]), "r"(a[1]), "r"(a[2]), "r"(a[3]), "r"(b0), "r"(b1));
}

// ---------------- dual-output bf16x3 tensor GEMM + bias ----------------
// C = A @ B + bias with A = Ah+Al (bf16 split, row-major), B pre-split k-paired words.
// 3 passes: Ah*Bh + Al*Bh + Ah*Bl (~1e-5 rel accuracy).
// Block tile 128x64, BK=32, 256 threads (8 warps: 4x2 of 32x32 warp tiles).
// Small warp tile keeps regs < 128 -> 2 CTAs/SM (R5 version was 140 regs, occ 12%).
__global__ __launch_bounds__(256, 2)
void k_gemm_bf16x3_dual(const __nv_bfloat16* __restrict__ Agh, const __nv_bfloat16* __restrict__ Agl,
                        const uint32_t* __restrict__ B1h, const uint32_t* __restrict__ B1l,
                        const float* __restrict__ b1, float* __restrict__ C1,
                        const uint32_t* __restrict__ B2h, const uint32_t* __restrict__ B2l,
                        const float* __restrict__ b2, float* __restrict__ C2,
                        int Nrows, int K, int M) {
    const int nbx = M >> 6;
    int bx = blockIdx.x;
    const uint32_t* Bh = B1h; const uint32_t* Bl = B1l;
    const float* bias = b1; float* C = C1;
    if (bx >= nbx) { bx -= nbx; Bh = B2h; Bl = B2l; bias = b2; C = C2; }
    const int row0 = blockIdx.y << 7;
    const int col0 = bx << 6;
    const int K2 = K >> 1;                 // words per A row

    __shared__ uint32_t sA[2][128][20];    // [split][m][k2-word], pad 20 -> conflict-free
    __shared__ uint32_t sB[2][16][72];     // [split][k2-word][n], pad 72 -> conflict-free

    const int tid = threadIdx.x;
    const int lane = tid & 31;
    const int wid = tid >> 5;
    const int wm = wid & 3;                // 0..3 -> 32 rows
    const int wn = wid >> 2;               // 0..1 -> 32 cols
    const int g = lane >> 2;               // 0..7
    const int t = lane & 3;                // 0..3

    const uint32_t* Ahw = (const uint32_t*)Agh;
    const uint32_t* Alw = (const uint32_t*)Agl;

    float acc[2][4][4];
#pragma unroll
    for (int i = 0; i < 2; i++)
#pragma unroll
        for (int j = 0; j < 4; j++)
#pragma unroll
            for (int q = 0; q < 4; q++) acc[i][j][q] = 0.f;

    const int ktiles = K >> 5;
    for (int kt = 0; kt < ktiles; kt++) {
        const int kk2 = kt << 4;
        // A tile: 128 rows x 16 words per split; 512 uint4 per split
#pragma unroll
        for (int i = 0; i < 2; i++) {
            int f = tid + i * 256;
            int r = f >> 2;
            int c4 = (f & 3) * 4;
            uint4 vh = make_uint4(0u, 0u, 0u, 0u), vl = make_uint4(0u, 0u, 0u, 0u);
            if (row0 + r < Nrows) {
                long w = (long)(row0 + r) * K2 + kk2 + c4;
                vh = *(const uint4*)(Ahw + w);
                vl = *(const uint4*)(Alw + w);
            }
            *(uint4*)&sA[0][r][c4] = vh;
            *(uint4*)&sA[1][r][c4] = vl;
        }
        // B tile: 16 k2-rows x 64 words per split -> 256 uint4 per split
        {
            int r = tid >> 4;
            int c4 = (tid & 15) * 4;
            long w = (long)(kk2 + r) * M + col0 + c4;
            *(uint4*)&sB[0][r][c4] = *(const uint4*)(Bh + w);
            *(uint4*)&sB[1][r][c4] = *(const uint4*)(Bl + w);
        }
        __syncthreads();

#pragma unroll
        for (int k16 = 0; k16 < 2; k16++) {
            const int kb = k16 * 8;
            uint32_t af[2][2][4];   // [split][mt][frag]
#pragma unroll
            for (int s = 0; s < 2; s++)
#pragma unroll
                for (int mt = 0; mt < 2; mt++) {
                    const int mr = wm * 32 + mt * 16;
                    af[s][mt][0] = sA[s][mr + g][kb + t];
                    af[s][mt][1] = sA[s][mr + 8 + g][kb + t];
                    af[s][mt][2] = sA[s][mr + g][kb + 4 + t];
                    af[s][mt][3] = sA[s][mr + 8 + g][kb + 4 + t];
                }
#pragma unroll
            for (int nt = 0; nt < 4; nt++) {
                const int nc = wn * 32 + nt * 8 + g;
                uint32_t bh0 = sB[0][kb + t][nc];
                uint32_t bh1 = sB[0][kb + 4 + t][nc];
                uint32_t bl0 = sB[1][kb + t][nc];
                uint32_t bl1 = sB[1][kb + 4 + t][nc];
#pragma unroll
                for (int mt = 0; mt < 2; mt++) {
                    mma_bf16(acc[mt][nt], af[0][mt], bh0, bh1);
                    mma_bf16(acc[mt][nt], af[1][mt], bh0, bh1);
                    mma_bf16(acc[mt][nt], af[0][mt], bl0, bl1);
                }
            }
        }
        __syncthreads();
    }

    // epilogue: bias + guarded float2 stores (m16n8 C layout)
#pragma unroll
    for (int nt = 0; nt < 4; nt++) {
        const int c = col0 + wn * 32 + nt * 8 + t * 2;
        const float2 bv = *(const float2*)(bias + c);
#pragma unroll
        for (int mt = 0; mt < 2; mt++) {
            const int r0 = row0 + wm * 32 + mt * 16 + g;
            if (r0 < Nrows) {
                float2 o; o.x = acc[mt][nt][0] + bv.x; o.y = acc[mt][nt][1] + bv.y;
                *(float2*)(C + (long)r0 * M + c) = o;
            }
            if (r0 + 8 < Nrows) {
                float2 o; o.x = acc[mt][nt][2] + bv.x; o.y = acc[mt][nt][3] + bv.y;
                *(float2*)(C + (long)(r0 + 8) * M + c) = o;
            }
        }
    }
}

// ---------------- fused GATv2 edge-softmax + aggregate + head-maxpool ----------------
// block = 128 threads = 4 warps = 4 heads; grid-stride over nodes.
// Straight-line online softmax (R4-proven; NO branch -> loads pipeline across edges).
// SPLIT: write result as bf16 hi/lo (feeds next GEMM); else fp32.
template <int D, bool SPLIT>
__global__ void k_gat(const float* __restrict__ fs, const float* __restrict__ fd,
                      const float* __restrict__ attn, float* __restrict__ hout,
                      __nv_bfloat16* __restrict__ hh, __nv_bfloat16* __restrict__ hl) {
    constexpr int VPT = D / 32;
    constexpr int HD = NH * D;
    __shared__ float sh[NH][D];
    const int lane = threadIdx.x & 31;
    const int h = threadIdx.x >> 5;

    float areg[VPT];
#pragma unroll
    for (int i = 0; i < VPT; i++) areg[i] = attn[h * D + i * 32 + lane];

    for (int v = blockIdx.x; v < NN; v += gridDim.x) {
        float fdr[VPT];
        const float* fdp = fd + (long)v * HD + h * D;
#pragma unroll
        for (int i = 0; i < VPT; i++) fdr[i] = fdp[i * 32 + lane];

        const int s0 = g_rs[v], s1 = g_rs[v + 1];
        float m = -INF_, ssum = 0.f;
        float acc[VPT];
#pragma unroll
        for (int i = 0; i < VPT; i++) acc[i] = 0.f;

        for (int idx = s0; idx < s1; idx++) {
            int u = g_adj[idx];
            const float* fsp = fs + (long)u * HD + h * D;
            float fu[VPT];
            float p = 0.f;
#pragma unroll
            for (int i = 0; i < VPT; i++) {
                fu[i] = fsp[i * 32 + lane];
                float t = fu[i] + fdr[i];
                t = t > 0.f ? t : SLOPE * t;
                p += areg[i] * t;
            }
#pragma unroll
            for (int o = 16; o; o >>= 1) p += __shfl_xor_sync(0xffffffffu, p, o);
            float mn = fmaxf(m, p);
            float sc = __expf(m - mn);       // first iter: exp(-inf) = 0
            float pe = __expf(p - mn);
            ssum = ssum * sc + pe;
#pragma unroll
            for (int i = 0; i < VPT; i++) acc[i] = acc[i] * sc + pe * fu[i];
            m = mn;
        }
        float inv = (s1 > s0) ? 1.f / ssum : 0.f;
#pragma unroll
        for (int i = 0; i < VPT; i++) sh[h][i * 32 + lane] = acc[i] * inv;
        __syncthreads();
        for (int d = threadIdx.x; d < D; d += blockDim.x) {
            float mx = fmaxf(fmaxf(sh[0][d], sh[1][d]), fmaxf(sh[2][d], sh[3][d]));
            if (SPLIT) {
                __nv_bfloat16 hi = __float2bfloat16_rn(mx);
                hh[(long)v * D + d] = hi;
                hl[(long)v * D + d] = __float2bfloat16_rn(mx - __bfloat162float(hi));
            } else {
                hout[(long)v * D + d] = mx;
            }
        }
        __syncthreads();
    }
}

// ---------------- global attention pooling: one block (128 thr) per graph ----------------
__global__ void k_pool(const float* __restrict__ gw, const float* __restrict__ gb,
                       float* __restrict__ out, int npg) {
    const int g = blockIdx.x;
    const int tid = threadIdx.x;
    const int lane = tid & 31;
    const int w = tid >> 5;
    extern __shared__ float sg[];
    __shared__ float red[16];
    const int base = g * npg;

    float gwr[4];
#pragma unroll
    for (int i = 0; i < 4; i++) gwr[i] = gw[i * 32 + lane];
    const float gbv = gb[0];

    for (int v = w; v < npg; v += 4) {
        const float* hp = g_h2 + (long)(base + v) * H2D;
        float p = 0.f;
#pragma unroll
        for (int i = 0; i < 4; i++) p += gwr[i] * hp[i * 32 + lane];
#pragma unroll
        for (int o = 16; o; o >>= 1) p += __shfl_xor_sync(0xffffffffu, p, o);
        if (lane == 0) sg[v] = p + gbv;
    }
    __syncthreads();

    float mx = -INF_;
    for (int v = tid; v < npg; v += 128) mx = fmaxf(mx, sg[v]);
#pragma unroll
    for (int o = 16; o; o >>= 1) mx = fmaxf(mx, __shfl_xor_sync(0xffffffffu, mx, o));
    if (lane == 0) red[w] = mx;
    __syncthreads();
    if (tid == 0) red[8] = fmaxf(fmaxf(red[0], red[1]), fmaxf(red[2], red[3]));
    __syncthreads();
    const float M = red[8];

    float ss = 0.f;
    for (int v = tid; v < npg; v += 128) {
        float e = __expf(sg[v] - M);
        sg[v] = e;
        ss += e;
    }
#pragma unroll
    for (int o = 16; o; o >>= 1) ss += __shfl_xor_sync(0xffffffffu, ss, o);
    if (lane == 0) red[w] = ss;
    __syncthreads();
    if (tid == 0) red[9] = red[0] + red[1] + red[2] + red[3];
    __syncthreads();
    const float inv = 1.f / red[9];

    float accD = 0.f;
    for (int v = 0; v < npg; v++)
        accD += sg[v] * g_h2[(long)(base + v) * H2D + tid];
    out[g * H2D + tid] = accD * inv;
}

// ---------------- launch ----------------
extern "C" void kernel_launch(void* const* d_in, const int* in_sizes, int n_in,
                              void* d_out, int out_size) {
    const float* x    = (const float*)d_in[0];
    const int* esrc   = (const int*)d_in[1];
    const int* edst   = (const int*)d_in[2];
    // d_in[3] = node_graph (contiguous blocks; unused)
    const float* Wl1  = (const float*)d_in[4];
    const float* bl1  = (const float*)d_in[5];
    const float* Wr1  = (const float*)d_in[6];
    const float* br1  = (const float*)d_in[7];
    const float* at1  = (const float*)d_in[8];
    const float* Wl2  = (const float*)d_in[9];
    const float* bl2  = (const float*)d_in[10];
    const float* Wr2  = (const float*)d_in[11];
    const float* br2  = (const float*)d_in[12];
    const float* at2  = (const float*)d_in[13];
    const float* gw   = (const float*)d_in[14];
    const float* gb   = (const float*)d_in[15];

    const int E = in_sizes[1];
    const int N = in_sizes[0] / 128;
    const int G = out_size / H2D;
    const int npg = N / G;

    float *fs1, *fd1, *fs2, *fd2, *h2;
    __nv_bfloat16 *xh, *xl, *h1h, *h1l;
    uint32_t* wb;
    int* degp;
    cudaGetSymbolAddress((void**)&fs1, g_fs1);
    cudaGetSymbolAddress((void**)&fd1, g_fd1);
    cudaGetSymbolAddress((void**)&fs2, g_fs2);
    cudaGetSymbolAddress((void**)&fd2, g_fd2);
    cudaGetSymbolAddress((void**)&h2,  g_h2);
    cudaGetSymbolAddress((void**)&xh,  g_xh);
    cudaGetSymbolAddress((void**)&xl,  g_xl);
    cudaGetSymbolAddress((void**)&h1h, g_h1h);
    cudaGetSymbolAddress((void**)&h1l, g_h1l);
    cudaGetSymbolAddress((void**)&wb,  g_wb);
    cudaGetSymbolAddress((void**)&degp, g_deg);

    const int rowBlocks = (N + 127) / 128;

    // 0: split x
    k_split_f32<<<(N * 128 + 255) / 256, 256>>>(x, xh, xl, N * 128);
    // 1-2: split layer-1 weights (K=128 -> K2=64, M=256)
    k_split_w<<<(64 * 256 + 255) / 256, 256>>>(Wl1, wb + 0 * 16384, wb + 1 * 16384, 64, 256);
    k_split_w<<<(64 * 256 + 255) / 256, 256>>>(Wr1, wb + 2 * 16384, wb + 3 * 16384, 64, 256);
    // 3: layer-1 dual GEMM  (the ncu-profiled launch slot)
    {
        dim3 grid(2 * (NH * H1D / 64), rowBlocks);
        k_gemm_bf16x3_dual<<<grid, 256>>>(xh, xl,
                                          wb + 0 * 16384, wb + 1 * 16384, bl1, fs1,
                                          wb + 2 * 16384, wb + 3 * 16384, br1, fd1,
                                          N, 128, NH * H1D);
    }

    // ---- CSR build (deterministic) ----
    cudaMemsetAsync(degp, 0, NN * sizeof(int));
    k_hist<<<(E + 255) / 256, 256>>>(edst, E);
    k_scan<<<1, 1024>>>(E);
    k_scatter<<<(E + 255) / 256, 256>>>(edst, E);
    k_sortseg<<<(NN + 255) / 256, 256>>>();
    k_eid2src<<<(E + 255) / 256, 256>>>(esrc, E);

    // GAT layer 1 -> split h1
    k_gat<H1D, true><<<2368, 128>>>(fs1, fd1, at1, nullptr, h1h, h1l);

    // split layer-2 weights (K=64 -> K2=32, M=512)
    k_split_w<<<(32 * 512 + 255) / 256, 256>>>(Wl2, wb + 4 * 16384, wb + 5 * 16384, 32, 512);
    k_split_w<<<(32 * 512 + 255) / 256, 256>>>(Wr2, wb + 6 * 16384, wb + 7 * 16384, 32, 512);
    // layer-2 dual GEMM
    {
        dim3 grid(2 * (NH * H2D / 64), rowBlocks);
        k_gemm_bf16x3_dual<<<grid, 256>>>(h1h, h1l,
                                          wb + 4 * 16384, wb + 5 * 16384, bl2, fs2,
                                          wb + 6 * 16384, wb + 7 * 16384, br2, fd2,
                                          N, H1D, NH * H2D);
    }
    k_gat<H2D, false><<<2368, 128>>>(fs2, fd2, at2, h2, nullptr, nullptr);

    // pooling
    k_pool<<<G, 128, npg * sizeof(float)>>>(gw, gb, (float*)d_out, npg);
}

// round 7
// speedup vs baseline: 1.3864x; 1.3193x over previous
#include <cuda_runtime.h>
#include <cuda_bf16.h>
#include <math.h>
#include <stdint.h>

// ---------------- problem constants (fixed by the dataset) ----------------
#define NN   50000      // nodes
#define EE   500000     // edges
#define GG   50         // graphs
#define INF_ 3.402823466e+38f

#define H1D  64         // HID[0]
#define H2D  128        // HID[1]
#define NH   4          // heads
#define SLOPE 0.2f

// ---------------- scratch (device globals; no allocation) ----------------
__device__ float g_fs1[NN * NH * H1D];
__device__ float g_fd1[NN * NH * H1D];
__device__ float g_fs2[NN * NH * H2D];
__device__ float g_fd2[NN * NH * H2D];
__device__ float g_h2 [NN * H2D];

__device__ __nv_bfloat16 g_xh[NN * 128];   // x split
__device__ __nv_bfloat16 g_xl[NN * 128];
__device__ __nv_bfloat16 g_h1h[NN * H1D];  // h1 split (written by GAT-1 epilogue)
__device__ __nv_bfloat16 g_h1l[NN * H1D];
__device__ uint32_t g_wb[8][16384];        // weight splits, k-paired words

__device__ int g_deg[NN];
__device__ int g_rs [NN + 1];
__device__ int g_cur[NN];
__device__ int g_adj[EE];       // dst-sorted src list (CSR payload)

// ---------------- split converters ----------------
__global__ void k_split_f32(const float* __restrict__ src,
                            __nv_bfloat16* __restrict__ hi, __nv_bfloat16* __restrict__ lo, int n) {
    int i = blockIdx.x * blockDim.x + threadIdx.x;
    if (i < n) {
        float v = src[i];
        __nv_bfloat16 h = __float2bfloat16_rn(v);
        hi[i] = h;
        lo[i] = __float2bfloat16_rn(v - __bfloat162float(h));
    }
}

// W [K][M] fp32 -> paired words: out[k2*M + n] = pack(bf16(W[2k2][n]), bf16(W[2k2+1][n]))
__global__ void k_split_w(const float* __restrict__ W,
                          uint32_t* __restrict__ outh, uint32_t* __restrict__ outl,
                          int K2, int M) {
    int i = blockIdx.x * blockDim.x + threadIdx.x;
    if (i >= K2 * M) return;
    int k2 = i / M, n = i - k2 * M;
    float e0 = W[(2 * k2) * M + n];
    float e1 = W[(2 * k2 + 1) * M + n];
    __nv_bfloat16 h0 = __float2bfloat16_rn(e0);
    __nv_bfloat16 h1 = __float2bfloat16_rn(e1);
    __nv_bfloat16 l0 = __float2bfloat16_rn(e0 - __bfloat162float(h0));
    __nv_bfloat16 l1 = __float2bfloat16_rn(e1 - __bfloat162float(h1));
    uint32_t wh = (uint32_t)__bfloat16_as_ushort(h0) | ((uint32_t)__bfloat16_as_ushort(h1) << 16);
    uint32_t wl = (uint32_t)__bfloat16_as_ushort(l0) | ((uint32_t)__bfloat16_as_ushort(l1) << 16);
    outh[i] = wh;
    outl[i] = wl;
}

// ---------------- CSR build ----------------
__global__ void k_hist(const int* __restrict__ dst, int E) {
    int i = blockIdx.x * blockDim.x + threadIdx.x;
    if (i < E) atomicAdd(&g_deg[dst[i]], 1);
}

__global__ void k_scan(int E) {
    __shared__ int sm[1024];
    int tid = threadIdx.x;
    const int chunk = (NN + 1023) / 1024;
    int b = tid * chunk;
    int e = b + chunk; if (e > NN) e = NN;
    int s = 0;
    for (int i = b; i < e; i++) s += g_deg[i];
    sm[tid] = s;
    __syncthreads();
    for (int off = 1; off < 1024; off <<= 1) {
        int v = (tid >= off) ? sm[tid - off] : 0;
        __syncthreads();
        sm[tid] += v;
        __syncthreads();
    }
    int run = sm[tid] - s;   // exclusive prefix for this chunk
    for (int i = b; i < e; i++) {
        g_rs[i] = run;
        g_cur[i] = run;
        run += g_deg[i];
    }
    if (tid == 0) g_rs[NN] = E;
}

__global__ void k_scatter(const int* __restrict__ dst, int E) {
    int i = blockIdx.x * blockDim.x + threadIdx.x;
    if (i < E) {
        int p = atomicAdd(&g_cur[dst[i]], 1);
        g_adj[p] = i;
    }
}

// warp-per-node deterministic sort of edge ids (bitonic-32 in registers via shfl).
// Poisson(10) degrees: d<=32 essentially always; serial fallback kept for safety.
__global__ void k_sortseg_warp() {
    const int lane = threadIdx.x & 31;
    const int v = blockIdx.x * (blockDim.x >> 5) + (threadIdx.x >> 5);
    if (v >= NN) return;
    const int s = g_rs[v], e = g_rs[v + 1];
    const int d = e - s;
    if (d <= 1) return;
    if (d <= 32) {
        int key = (lane < d) ? g_adj[s + lane] : 0x7FFFFFFF;
#pragma unroll
        for (int k = 2; k <= 32; k <<= 1) {
#pragma unroll
            for (int j = k >> 1; j > 0; j >>= 1) {
                int o = __shfl_xor_sync(0xffffffffu, key, j);
                bool up = ((lane & k) == 0);
                bool low = ((lane & j) == 0);
                int mn = min(key, o), mx = max(key, o);
                key = (low == up) ? mn : mx;
            }
        }
        if (lane < d) g_adj[s + lane] = key;
    } else if (lane == 0) {
        for (int i = s + 1; i < e; i++) {
            int key = g_adj[i];
            int j = i - 1;
            while (j >= s && g_adj[j] > key) { g_adj[j + 1] = g_adj[j]; j--; }
            g_adj[j + 1] = key;
        }
    }
}

__global__ void k_eid2src(const int* __restrict__ src, int E) {
    int i = blockIdx.x * blockDim.x + threadIdx.x;
    if (i < E) g_adj[i] = src[g_adj[i]];
}

// ---------------- bf16 mma helper ----------------
__device__ __forceinline__ void mma_bf16(float c[4], const uint32_t a[4], uint32_t b0, uint32_t b1) {
    asm("mma.sync.aligned.m16n8k16.row.col.f32.bf16.bf16.f32 "
        "{%0,%1,%2,%3}, {%4,%5,%6,%7}, {%8,%9}, {%0,%1,%2,%3};"
        : "+f"(c[0]), "+f"(c[1]), "+f"(c[2]), "+f"(c[3])
        : "r"(a[0]), "r"(a[1]), "r"(a[2]), "r"(a[3]), "r"(b0), "r"(b1));
}

// ---------------- dual-output bf16x3 tensor GEMM + bias (unchanged, measured 136us) ----
__global__ __launch_bounds__(256, 2)
void k_gemm_bf16x3_dual(const __nv_bfloat16* __restrict__ Agh, const __nv_bfloat16* __restrict__ Agl,
                        const uint32_t* __restrict__ B1h, const uint32_t* __restrict__ B1l,
                        const float* __restrict__ b1, float* __restrict__ C1,
                        const uint32_t* __restrict__ B2h, const uint32_t* __restrict__ B2l,
                        const float* __restrict__ b2, float* __restrict__ C2,
                        int Nrows, int K, int M) {
    const int nbx = M >> 6;
    int bx = blockIdx.x;
    const uint32_t* Bh = B1h; const uint32_t* Bl = B1l;
    const float* bias = b1; float* C = C1;
    if (bx >= nbx) { bx -= nbx; Bh = B2h; Bl = B2l; bias = b2; C = C2; }
    const int row0 = blockIdx.y << 7;
    const int col0 = bx << 6;
    const int K2 = K >> 1;

    __shared__ uint32_t sA[2][128][20];
    __shared__ uint32_t sB[2][16][72];

    const int tid = threadIdx.x;
    const int lane = tid & 31;
    const int wid = tid >> 5;
    const int wm = wid & 3;
    const int wn = wid >> 2;
    const int g = lane >> 2;
    const int t = lane & 3;

    const uint32_t* Ahw = (const uint32_t*)Agh;
    const uint32_t* Alw = (const uint32_t*)Agl;

    float acc[2][4][4];
#pragma unroll
    for (int i = 0; i < 2; i++)
#pragma unroll
        for (int j = 0; j < 4; j++)
#pragma unroll
            for (int q = 0; q < 4; q++) acc[i][j][q] = 0.f;

    const int ktiles = K >> 5;
    for (int kt = 0; kt < ktiles; kt++) {
        const int kk2 = kt << 4;
#pragma unroll
        for (int i = 0; i < 2; i++) {
            int f = tid + i * 256;
            int r = f >> 2;
            int c4 = (f & 3) * 4;
            uint4 vh = make_uint4(0u, 0u, 0u, 0u), vl = make_uint4(0u, 0u, 0u, 0u);
            if (row0 + r < Nrows) {
                long w = (long)(row0 + r) * K2 + kk2 + c4;
                vh = *(const uint4*)(Ahw + w);
                vl = *(const uint4*)(Alw + w);
            }
            *(uint4*)&sA[0][r][c4] = vh;
            *(uint4*)&sA[1][r][c4] = vl;
        }
        {
            int r = tid >> 4;
            int c4 = (tid & 15) * 4;
            long w = (long)(kk2 + r) * M + col0 + c4;
            *(uint4*)&sB[0][r][c4] = *(const uint4*)(Bh + w);
            *(uint4*)&sB[1][r][c4] = *(const uint4*)(Bl + w);
        }
        __syncthreads();

#pragma unroll
        for (int k16 = 0; k16 < 2; k16++) {
            const int kb = k16 * 8;
            uint32_t af[2][2][4];
#pragma unroll
            for (int s = 0; s < 2; s++)
#pragma unroll
                for (int mt = 0; mt < 2; mt++) {
                    const int mr = wm * 32 + mt * 16;
                    af[s][mt][0] = sA[s][mr + g][kb + t];
                    af[s][mt][1] = sA[s][mr + 8 + g][kb + t];
                    af[s][mt][2] = sA[s][mr + g][kb + 4 + t];
                    af[s][mt][3] = sA[s][mr + 8 + g][kb + 4 + t];
                }
#pragma unroll
            for (int nt = 0; nt < 4; nt++) {
                const int nc = wn * 32 + nt * 8 + g;
                uint32_t bh0 = sB[0][kb + t][nc];
                uint32_t bh1 = sB[0][kb + 4 + t][nc];
                uint32_t bl0 = sB[1][kb + t][nc];
                uint32_t bl1 = sB[1][kb + 4 + t][nc];
#pragma unroll
                for (int mt = 0; mt < 2; mt++) {
                    mma_bf16(acc[mt][nt], af[0][mt], bh0, bh1);
                    mma_bf16(acc[mt][nt], af[1][mt], bh0, bh1);
                    mma_bf16(acc[mt][nt], af[0][mt], bl0, bl1);
                }
            }
        }
        __syncthreads();
    }

#pragma unroll
    for (int nt = 0; nt < 4; nt++) {
        const int c = col0 + wn * 32 + nt * 8 + t * 2;
        const float2 bv = *(const float2*)(bias + c);
#pragma unroll
        for (int mt = 0; mt < 2; mt++) {
            const int r0 = row0 + wm * 32 + mt * 16 + g;
            if (r0 < Nrows) {
                float2 o; o.x = acc[mt][nt][0] + bv.x; o.y = acc[mt][nt][1] + bv.y;
                *(float2*)(C + (long)r0 * M + c) = o;
            }
            if (r0 + 8 < Nrows) {
                float2 o; o.x = acc[mt][nt][2] + bv.x; o.y = acc[mt][nt][3] + bv.y;
                *(float2*)(C + (long)(r0 + 8) * M + c) = o;
            }
        }
    }
}

// ---------------- 4-edge-batched fused GATv2 ----------------
// block = 128 thr = 4 warps = 4 heads. Warp splits into 4 lane-groups of 8;
// each group computes one edge per batch -> 4 edges per online-softmax update.
// Kills the per-edge shfl+exp serial chain (5 shfls + 2 exps per 4 edges) and
// gives 4x load MLP. Cross-group accumulator reduce once per node.
template <int D, bool SPLIT>
__global__ void k_gat(const float* __restrict__ fs, const float* __restrict__ fd,
                      const float* __restrict__ attn, float* __restrict__ hout,
                      __nv_bfloat16* __restrict__ hh, __nv_bfloat16* __restrict__ hl) {
    constexpr int VP = D / 8;            // elems per lane (lane covers elems j*8 + l8)
    constexpr int HD = NH * D;
    __shared__ float sh[NH][D];
    const int lane = threadIdx.x & 31;
    const int h = threadIdx.x >> 5;
    const int l8 = lane & 7;
    const int grp = lane >> 3;

    float areg[VP];
#pragma unroll
    for (int j = 0; j < VP; j++) areg[j] = attn[h * D + j * 8 + l8];

    for (int v = blockIdx.x; v < NN; v += gridDim.x) {
        float fdr[VP];
        const float* fdp = fd + (long)v * HD + h * D;
#pragma unroll
        for (int j = 0; j < VP; j++) fdr[j] = fdp[j * 8 + l8];

        const int s0 = g_rs[v], s1 = g_rs[v + 1];
        float m = -INF_, ssum = 0.f;
        float acc[VP];
#pragma unroll
        for (int j = 0; j < VP; j++) acc[j] = 0.f;

        for (int s = s0; s < s1; s += 4) {
            const int slot = s + grp;
            const bool valid = slot < s1;
            const int u = g_adj[valid ? slot : s0];
            const float* fsp = fs + (long)u * HD + h * D;
            float fu[VP];
            float p = 0.f;
#pragma unroll
            for (int j = 0; j < VP; j++) {
                fu[j] = fsp[j * 8 + l8];
                float t = fu[j] + fdr[j];
                t = t > 0.f ? t : SLOPE * t;
                p += areg[j] * t;
            }
            // intra-group (8-lane) dot reduce -> all 8 lanes hold the logit
            p += __shfl_xor_sync(0xffffffffu, p, 1);
            p += __shfl_xor_sync(0xffffffffu, p, 2);
            p += __shfl_xor_sync(0xffffffffu, p, 4);
            if (!valid) p = -INF_;
            // batch max across 4 groups
            float q = fmaxf(p, __shfl_xor_sync(0xffffffffu, p, 8));
            q = fmaxf(q, __shfl_xor_sync(0xffffffffu, q, 16));
            // one online-softmax update per 4-edge batch
            float mn = fmaxf(m, q);
            float sc = __expf(m - mn);     // first batch: exp(-3.4e38) = 0
            float pe = __expf(p - mn);     // invalid: exp(-3.4e38) = 0
            ssum = ssum * sc + pe;
#pragma unroll
            for (int j = 0; j < VP; j++) acc[j] = acc[j] * sc + pe * fu[j];
            m = mn;
        }
        // reduce partial sums across the 4 groups
        ssum += __shfl_xor_sync(0xffffffffu, ssum, 8);
        ssum += __shfl_xor_sync(0xffffffffu, ssum, 16);
#pragma unroll
        for (int j = 0; j < VP; j++) {
            acc[j] += __shfl_xor_sync(0xffffffffu, acc[j], 8);
            acc[j] += __shfl_xor_sync(0xffffffffu, acc[j], 16);
        }
        const float inv = (s1 > s0) ? 1.f / ssum : 0.f;
        if (grp == 0) {
#pragma unroll
            for (int j = 0; j < VP; j++) sh[h][j * 8 + l8] = acc[j] * inv;
        }
        __syncthreads();
        for (int d = threadIdx.x; d < D; d += blockDim.x) {
            float mx = fmaxf(fmaxf(sh[0][d], sh[1][d]), fmaxf(sh[2][d], sh[3][d]));
            if (SPLIT) {
                __nv_bfloat16 hi = __float2bfloat16_rn(mx);
                hh[(long)v * D + d] = hi;
                hl[(long)v * D + d] = __float2bfloat16_rn(mx - __bfloat162float(hi));
            } else {
                hout[(long)v * D + d] = mx;
            }
        }
        __syncthreads();
    }
}

// ---------------- global attention pooling: one block (128 thr) per graph ----------------
__global__ void k_pool(const float* __restrict__ gw, const float* __restrict__ gb,
                       float* __restrict__ out, int npg) {
    const int g = blockIdx.x;
    const int tid = threadIdx.x;
    const int lane = tid & 31;
    const int w = tid >> 5;
    extern __shared__ float sg[];
    __shared__ float red[16];
    const int base = g * npg;

    float gwr[4];
#pragma unroll
    for (int i = 0; i < 4; i++) gwr[i] = gw[i * 32 + lane];
    const float gbv = gb[0];

    for (int v = w; v < npg; v += 4) {
        const float* hp = g_h2 + (long)(base + v) * H2D;
        float p = 0.f;
#pragma unroll
        for (int i = 0; i < 4; i++) p += gwr[i] * hp[i * 32 + lane];
#pragma unroll
        for (int o = 16; o; o >>= 1) p += __shfl_xor_sync(0xffffffffu, p, o);
        if (lane == 0) sg[v] = p + gbv;
    }
    __syncthreads();

    float mx = -INF_;
    for (int v = tid; v < npg; v += 128) mx = fmaxf(mx, sg[v]);
#pragma unroll
    for (int o = 16; o; o >>= 1) mx = fmaxf(mx, __shfl_xor_sync(0xffffffffu, mx, o));
    if (lane == 0) red[w] = mx;
    __syncthreads();
    if (tid == 0) red[8] = fmaxf(fmaxf(red[0], red[1]), fmaxf(red[2], red[3]));
    __syncthreads();
    const float M = red[8];

    float ss = 0.f;
    for (int v = tid; v < npg; v += 128) {
        float e = __expf(sg[v] - M);
        sg[v] = e;
        ss += e;
    }
#pragma unroll
    for (int o = 16; o; o >>= 1) ss += __shfl_xor_sync(0xffffffffu, ss, o);
    if (lane == 0) red[w] = ss;
    __syncthreads();
    if (tid == 0) red[9] = red[0] + red[1] + red[2] + red[3];
    __syncthreads();
    const float inv = 1.f / red[9];

    float accD = 0.f;
    for (int v = 0; v < npg; v++)
        accD += sg[v] * g_h2[(long)(base + v) * H2D + tid];
    out[g * H2D + tid] = accD * inv;
}

// ---------------- launch ----------------
extern "C" void kernel_launch(void* const* d_in, const int* in_sizes, int n_in,
                              void* d_out, int out_size) {
    const float* x    = (const float*)d_in[0];
    const int* esrc   = (const int*)d_in[1];
    const int* edst   = (const int*)d_in[2];
    // d_in[3] = node_graph (contiguous blocks; unused)
    const float* Wl1  = (const float*)d_in[4];
    const float* bl1  = (const float*)d_in[5];
    const float* Wr1  = (const float*)d_in[6];
    const float* br1  = (const float*)d_in[7];
    const float* at1  = (const float*)d_in[8];
    const float* Wl2  = (const float*)d_in[9];
    const float* bl2  = (const float*)d_in[10];
    const float* Wr2  = (const float*)d_in[11];
    const float* br2  = (const float*)d_in[12];
    const float* at2  = (const float*)d_in[13];
    const float* gw   = (const float*)d_in[14];
    const float* gb   = (const float*)d_in[15];

    const int E = in_sizes[1];
    const int N = in_sizes[0] / 128;
    const int G = out_size / H2D;
    const int npg = N / G;

    float *fs1, *fd1, *fs2, *fd2, *h2;
    __nv_bfloat16 *xh, *xl, *h1h, *h1l;
    uint32_t* wb;
    int* degp;
    cudaGetSymbolAddress((void**)&fs1, g_fs1);
    cudaGetSymbolAddress((void**)&fd1, g_fd1);
    cudaGetSymbolAddress((void**)&fs2, g_fs2);
    cudaGetSymbolAddress((void**)&fd2, g_fd2);
    cudaGetSymbolAddress((void**)&h2,  g_h2);
    cudaGetSymbolAddress((void**)&xh,  g_xh);
    cudaGetSymbolAddress((void**)&xl,  g_xl);
    cudaGetSymbolAddress((void**)&h1h, g_h1h);
    cudaGetSymbolAddress((void**)&h1l, g_h1l);
    cudaGetSymbolAddress((void**)&wb,  g_wb);
    cudaGetSymbolAddress((void**)&degp, g_deg);

    const int rowBlocks = (N + 127) / 128;

    // ---- CSR build first (deterministic); sortseg is the 4th kernel -> profiled ----
    cudaMemsetAsync(degp, 0, NN * sizeof(int));
    k_hist<<<(E + 255) / 256, 256>>>(edst, E);
    k_scan<<<1, 1024>>>(E);
    k_scatter<<<(E + 255) / 256, 256>>>(edst, E);
    k_sortseg_warp<<<(NN + 3) / 4, 128>>>();
    k_eid2src<<<(E + 255) / 256, 256>>>(esrc, E);

    // ---- splits ----
    k_split_f32<<<(N * 128 + 255) / 256, 256>>>(x, xh, xl, N * 128);
    k_split_w<<<(64 * 256 + 255) / 256, 256>>>(Wl1, wb + 0 * 16384, wb + 1 * 16384, 64, 256);
    k_split_w<<<(64 * 256 + 255) / 256, 256>>>(Wr1, wb + 2 * 16384, wb + 3 * 16384, 64, 256);

    // ---- layer 1 ----
    {
        dim3 grid(2 * (NH * H1D / 64), rowBlocks);
        k_gemm_bf16x3_dual<<<grid, 256>>>(xh, xl,
                                          wb + 0 * 16384, wb + 1 * 16384, bl1, fs1,
                                          wb + 2 * 16384, wb + 3 * 16384, br1, fd1,
                                          N, 128, NH * H1D);
    }
    k_gat<H1D, true><<<2368, 128>>>(fs1, fd1, at1, nullptr, h1h, h1l);

    // ---- layer 2 ----
    k_split_w<<<(32 * 512 + 255) / 256, 256>>>(Wl2, wb + 4 * 16384, wb + 5 * 16384, 32, 512);
    k_split_w<<<(32 * 512 + 255) / 256, 256>>>(Wr2, wb + 6 * 16384, wb + 7 * 16384, 32, 512);
    {
        dim3 grid(2 * (NH * H2D / 64), rowBlocks);
        k_gemm_bf16x3_dual<<<grid, 256>>>(h1h, h1l,
                                          wb + 4 * 16384, wb + 5 * 16384, bl2, fs2,
                                          wb + 6 * 16384, wb + 7 * 16384, br2, fd2,
                                          N, H1D, NH * H2D);
    }
    k_gat<H2D, false><<<2368, 128>>>(fs2, fd2, at2, h2, nullptr, nullptr);

    // ---- pooling ----
    k_pool<<<G, 128, npg * sizeof(float)>>>(gw, gb, (float*)d_out, npg);
}

// round 8
// speedup vs baseline: 1.5694x; 1.1320x over previous
#include <cuda_runtime.h>
#include <cuda_bf16.h>
#include <math.h>
#include <stdint.h>

// ---------------- problem constants (fixed by the dataset) ----------------
#define NN   50000      // nodes
#define EE   500000     // edges
#define GG   50         // graphs
#define INF_ 3.402823466e+38f

#define H1D  64         // HID[0]
#define H2D  128        // HID[1]
#define NH   4          // heads
#define SLOPE 0.2f

// ---------------- scratch (device globals; no allocation) ----------------
__device__ float g_fs1[NN * NH * H1D];
__device__ float g_fd1[NN * NH * H1D];
__device__ float g_fs2[NN * NH * H2D];
__device__ float g_fd2[NN * NH * H2D];
__device__ float g_h2 [NN * H2D];

__device__ __nv_bfloat16 g_xh[NN * 128];   // x split
__device__ __nv_bfloat16 g_xl[NN * 128];
__device__ __nv_bfloat16 g_h1h[NN * H1D];  // h1 split (written by GAT-1 epilogue)
__device__ __nv_bfloat16 g_h1l[NN * H1D];
__device__ uint32_t g_wb[8][16384];        // weight splits, k-paired words

__device__ int g_deg[NN];
__device__ int g_rs [NN + 1];
__device__ int g_cur[NN];
__device__ int g_adj[EE];       // dst-sorted src list (CSR payload)

// ---------------- split converters ----------------
__global__ void k_split_f32(const float* __restrict__ src,
                            __nv_bfloat16* __restrict__ hi, __nv_bfloat16* __restrict__ lo, int n) {
    int i = blockIdx.x * blockDim.x + threadIdx.x;
    if (i < n) {
        float v = src[i];
        __nv_bfloat16 h = __float2bfloat16_rn(v);
        hi[i] = h;
        lo[i] = __float2bfloat16_rn(v - __bfloat162float(h));
    }
}

// W [K][M] fp32 -> paired words: out[k2*M + n] = pack(bf16(W[2k2][n]), bf16(W[2k2+1][n]))
__global__ void k_split_w(const float* __restrict__ W,
                          uint32_t* __restrict__ outh, uint32_t* __restrict__ outl,
                          int K2, int M) {
    int i = blockIdx.x * blockDim.x + threadIdx.x;
    if (i >= K2 * M) return;
    int k2 = i / M, n = i - k2 * M;
    float e0 = W[(2 * k2) * M + n];
    float e1 = W[(2 * k2 + 1) * M + n];
    __nv_bfloat16 h0 = __float2bfloat16_rn(e0);
    __nv_bfloat16 h1 = __float2bfloat16_rn(e1);
    __nv_bfloat16 l0 = __float2bfloat16_rn(e0 - __bfloat162float(h0));
    __nv_bfloat16 l1 = __float2bfloat16_rn(e1 - __bfloat162float(h1));
    uint32_t wh = (uint32_t)__bfloat16_as_ushort(h0) | ((uint32_t)__bfloat16_as_ushort(h1) << 16);
    uint32_t wl = (uint32_t)__bfloat16_as_ushort(l0) | ((uint32_t)__bfloat16_as_ushort(l1) << 16);
    outh[i] = wh;
    outl[i] = wl;
}

// ---------------- CSR build ----------------
__global__ void k_hist(const int* __restrict__ dst, int E) {
    int i = blockIdx.x * blockDim.x + threadIdx.x;
    if (i < E) atomicAdd(&g_deg[dst[i]], 1);
}

__global__ void k_scan(int E) {
    __shared__ int sm[1024];
    int tid = threadIdx.x;
    const int chunk = (NN + 1023) / 1024;
    int b = tid * chunk;
    int e = b + chunk; if (e > NN) e = NN;
    int s = 0;
    for (int i = b; i < e; i++) s += g_deg[i];
    sm[tid] = s;
    __syncthreads();
    for (int off = 1; off < 1024; off <<= 1) {
        int v = (tid >= off) ? sm[tid - off] : 0;
        __syncthreads();
        sm[tid] += v;
        __syncthreads();
    }
    int run = sm[tid] - s;   // exclusive prefix for this chunk
    for (int i = b; i < e; i++) {
        g_rs[i] = run;
        g_cur[i] = run;
        run += g_deg[i];
    }
    if (tid == 0) g_rs[NN] = E;
}

__global__ void k_scatter(const int* __restrict__ dst, int E) {
    int i = blockIdx.x * blockDim.x + threadIdx.x;
    if (i < E) {
        int p = atomicAdd(&g_cur[dst[i]], 1);
        g_adj[p] = i;
    }
}

// warp-per-node: bitonic sort of edge ids (determinism) fused with eid->src map.
__global__ void k_sortseg_src(const int* __restrict__ src) {
    const int lane = threadIdx.x & 31;
    const int v = blockIdx.x * (blockDim.x >> 5) + (threadIdx.x >> 5);
    if (v >= NN) return;
    const int s = g_rs[v], e = g_rs[v + 1];
    const int d = e - s;
    if (d <= 0) return;
    if (d <= 32) {
        int key = (lane < d) ? g_adj[s + lane] : 0x7FFFFFFF;
#pragma unroll
        for (int k = 2; k <= 32; k <<= 1) {
#pragma unroll
            for (int j = k >> 1; j > 0; j >>= 1) {
                int o = __shfl_xor_sync(0xffffffffu, key, j);
                bool up = ((lane & k) == 0);
                bool low = ((lane & j) == 0);
                int mn = min(key, o), mx = max(key, o);
                key = (low == up) ? mn : mx;
            }
        }
        if (lane < d) g_adj[s + lane] = src[key];
    } else if (lane == 0) {
        for (int i = s + 1; i < e; i++) {
            int key = g_adj[i];
            int j = i - 1;
            while (j >= s && g_adj[j] > key) { g_adj[j + 1] = g_adj[j]; j--; }
            g_adj[j + 1] = key;
        }
        for (int i = s; i < e; i++) g_adj[i] = src[g_adj[i]];
    }
}

// ---------------- bf16 mma helper ----------------
__device__ __forceinline__ void mma_bf16(float c[4], const uint32_t a[4], uint32_t b0, uint32_t b1) {
    asm("mma.sync.aligned.m16n8k16.row.col.f32.bf16.bf16.f32 "
        "{%0,%1,%2,%3}, {%4,%5,%6,%7}, {%8,%9}, {%0,%1,%2,%3};"
        : "+f"(c[0]), "+f"(c[1]), "+f"(c[2]), "+f"(c[3])
        : "r"(a[0]), "r"(a[1]), "r"(a[2]), "r"(a[3]), "r"(b0), "r"(b1));
}

// ---------------- dual-output bf16x3 tensor GEMM + bias ----------------
// launch_bounds(256,3): target <=84 regs for 3 CTAs/SM (was 104 regs / occ 24%).
__global__ __launch_bounds__(256, 3)
void k_gemm_bf16x3_dual(const __nv_bfloat16* __restrict__ Agh, const __nv_bfloat16* __restrict__ Agl,
                        const uint32_t* __restrict__ B1h, const uint32_t* __restrict__ B1l,
                        const float* __restrict__ b1, float* __restrict__ C1,
                        const uint32_t* __restrict__ B2h, const uint32_t* __restrict__ B2l,
                        const float* __restrict__ b2, float* __restrict__ C2,
                        int Nrows, int K, int M) {
    const int nbx = M >> 6;
    int bx = blockIdx.x;
    const uint32_t* Bh = B1h; const uint32_t* Bl = B1l;
    const float* bias = b1; float* C = C1;
    if (bx >= nbx) { bx -= nbx; Bh = B2h; Bl = B2l; bias = b2; C = C2; }
    const int row0 = blockIdx.y << 7;
    const int col0 = bx << 6;
    const int K2 = K >> 1;

    __shared__ uint32_t sA[2][128][20];
    __shared__ uint32_t sB[2][16][72];

    const int tid = threadIdx.x;
    const int lane = tid & 31;
    const int wid = tid >> 5;
    const int wm = wid & 3;
    const int wn = wid >> 2;
    const int g = lane >> 2;
    const int t = lane & 3;

    const uint32_t* Ahw = (const uint32_t*)Agh;
    const uint32_t* Alw = (const uint32_t*)Agl;

    float acc[2][4][4];
#pragma unroll
    for (int i = 0; i < 2; i++)
#pragma unroll
        for (int j = 0; j < 4; j++)
#pragma unroll
            for (int q = 0; q < 4; q++) acc[i][j][q] = 0.f;

    const int ktiles = K >> 5;
    for (int kt = 0; kt < ktiles; kt++) {
        const int kk2 = kt << 4;
#pragma unroll
        for (int i = 0; i < 2; i++) {
            int f = tid + i * 256;
            int r = f >> 2;
            int c4 = (f & 3) * 4;
            uint4 vh = make_uint4(0u, 0u, 0u, 0u), vl = make_uint4(0u, 0u, 0u, 0u);
            if (row0 + r < Nrows) {
                long w = (long)(row0 + r) * K2 + kk2 + c4;
                vh = *(const uint4*)(Ahw + w);
                vl = *(const uint4*)(Alw + w);
            }
            *(uint4*)&sA[0][r][c4] = vh;
            *(uint4*)&sA[1][r][c4] = vl;
        }
        {
            int r = tid >> 4;
            int c4 = (tid & 15) * 4;
            long w = (long)(kk2 + r) * M + col0 + c4;
            *(uint4*)&sB[0][r][c4] = *(const uint4*)(Bh + w);
            *(uint4*)&sB[1][r][c4] = *(const uint4*)(Bl + w);
        }
        __syncthreads();

#pragma unroll
        for (int k16 = 0; k16 < 2; k16++) {
            const int kb = k16 * 8;
            uint32_t af[2][2][4];
#pragma unroll
            for (int s = 0; s < 2; s++)
#pragma unroll
                for (int mt = 0; mt < 2; mt++) {
                    const int mr = wm * 32 + mt * 16;
                    af[s][mt][0] = sA[s][mr + g][kb + t];
                    af[s][mt][1] = sA[s][mr + 8 + g][kb + t];
                    af[s][mt][2] = sA[s][mr + g][kb + 4 + t];
                    af[s][mt][3] = sA[s][mr + 8 + g][kb + 4 + t];
                }
#pragma unroll
            for (int nt = 0; nt < 4; nt++) {
                const int nc = wn * 32 + nt * 8 + g;
                uint32_t bh0 = sB[0][kb + t][nc];
                uint32_t bh1 = sB[0][kb + 4 + t][nc];
                uint32_t bl0 = sB[1][kb + t][nc];
                uint32_t bl1 = sB[1][kb + 4 + t][nc];
#pragma unroll
                for (int mt = 0; mt < 2; mt++) {
                    mma_bf16(acc[mt][nt], af[0][mt], bh0, bh1);
                    mma_bf16(acc[mt][nt], af[1][mt], bh0, bh1);
                    mma_bf16(acc[mt][nt], af[0][mt], bl0, bl1);
                }
            }
        }
        __syncthreads();
    }

#pragma unroll
    for (int nt = 0; nt < 4; nt++) {
        const int c = col0 + wn * 32 + nt * 8 + t * 2;
        const float2 bv = *(const float2*)(bias + c);
#pragma unroll
        for (int mt = 0; mt < 2; mt++) {
            const int r0 = row0 + wm * 32 + mt * 16 + g;
            if (r0 < Nrows) {
                float2 o; o.x = acc[mt][nt][0] + bv.x; o.y = acc[mt][nt][1] + bv.y;
                *(float2*)(C + (long)r0 * M + c) = o;
            }
            if (r0 + 8 < Nrows) {
                float2 o; o.x = acc[mt][nt][2] + bv.x; o.y = acc[mt][nt][3] + bv.y;
                *(float2*)(C + (long)(r0 + 8) * M + c) = o;
            }
        }
    }
}

// ---------------- 4-edge-batched fused GATv2, float4 gathers ----------------
// block = 128 thr = 4 warps = 4 heads; warp splits into 4 groups of 8 lanes,
// one edge per group per batch. Each lane loads float4 (LDG.128): 4x fewer
// load instrs and full 128B sectors vs the R7 strided-32b version.
template <int D, bool SPLIT>
__global__ void k_gat(const float* __restrict__ fs, const float* __restrict__ fd,
                      const float* __restrict__ attn, float* __restrict__ hout,
                      __nv_bfloat16* __restrict__ hh, __nv_bfloat16* __restrict__ hl) {
    constexpr int VP4 = D / 32;          // float4 chunks per lane
    constexpr int HD = NH * D;
    __shared__ float sh[NH][D];
    const int lane = threadIdx.x & 31;
    const int h = threadIdx.x >> 5;
    const int l8 = lane & 7;
    const int grp = lane >> 3;
    const int off0 = l8 * 4;             // lane covers elems j*32 + l8*4 .. +3

    float4 areg[VP4];
#pragma unroll
    for (int j = 0; j < VP4; j++)
        areg[j] = *(const float4*)(attn + h * D + j * 32 + off0);

    for (int v = blockIdx.x; v < NN; v += gridDim.x) {
        float4 fdr[VP4];
        const float* fdp = fd + (long)v * HD + h * D;
#pragma unroll
        for (int j = 0; j < VP4; j++) fdr[j] = *(const float4*)(fdp + j * 32 + off0);

        const int s0 = g_rs[v], s1 = g_rs[v + 1];
        float m = -INF_, ssum = 0.f;
        float4 acc[VP4];
#pragma unroll
        for (int j = 0; j < VP4; j++) acc[j] = make_float4(0.f, 0.f, 0.f, 0.f);

        for (int s = s0; s < s1; s += 4) {
            const int slot = s + grp;
            const bool valid = slot < s1;
            const int u = g_adj[valid ? slot : s0];
            const float* fsp = fs + (long)u * HD + h * D;
            float4 fu[VP4];
            float p = 0.f;
#pragma unroll
            for (int j = 0; j < VP4; j++) {
                fu[j] = *(const float4*)(fsp + j * 32 + off0);
                float t0 = fu[j].x + fdr[j].x; t0 = t0 > 0.f ? t0 : SLOPE * t0;
                float t1 = fu[j].y + fdr[j].y; t1 = t1 > 0.f ? t1 : SLOPE * t1;
                float t2 = fu[j].z + fdr[j].z; t2 = t2 > 0.f ? t2 : SLOPE * t2;
                float t3 = fu[j].w + fdr[j].w; t3 = t3 > 0.f ? t3 : SLOPE * t3;
                p += areg[j].x * t0 + areg[j].y * t1 + areg[j].z * t2 + areg[j].w * t3;
            }
            // intra-group (8-lane) dot reduce
            p += __shfl_xor_sync(0xffffffffu, p, 1);
            p += __shfl_xor_sync(0xffffffffu, p, 2);
            p += __shfl_xor_sync(0xffffffffu, p, 4);
            if (!valid) p = -INF_;
            // batch max across 4 groups
            float q = fmaxf(p, __shfl_xor_sync(0xffffffffu, p, 8));
            q = fmaxf(q, __shfl_xor_sync(0xffffffffu, q, 16));
            // one online-softmax update per 4-edge batch
            float mn = fmaxf(m, q);
            float sc = __expf(m - mn);
            float pe = __expf(p - mn);
            ssum = ssum * sc + pe;
#pragma unroll
            for (int j = 0; j < VP4; j++) {
                acc[j].x = acc[j].x * sc + pe * fu[j].x;
                acc[j].y = acc[j].y * sc + pe * fu[j].y;
                acc[j].z = acc[j].z * sc + pe * fu[j].z;
                acc[j].w = acc[j].w * sc + pe * fu[j].w;
            }
            m = mn;
        }
        // reduce partials across the 4 groups
        ssum += __shfl_xor_sync(0xffffffffu, ssum, 8);
        ssum += __shfl_xor_sync(0xffffffffu, ssum, 16);
#pragma unroll
        for (int j = 0; j < VP4; j++) {
            acc[j].x += __shfl_xor_sync(0xffffffffu, acc[j].x, 8);
            acc[j].x += __shfl_xor_sync(0xffffffffu, acc[j].x, 16);
            acc[j].y += __shfl_xor_sync(0xffffffffu, acc[j].y, 8);
            acc[j].y += __shfl_xor_sync(0xffffffffu, acc[j].y, 16);
            acc[j].z += __shfl_xor_sync(0xffffffffu, acc[j].z, 8);
            acc[j].z += __shfl_xor_sync(0xffffffffu, acc[j].z, 16);
            acc[j].w += __shfl_xor_sync(0xffffffffu, acc[j].w, 8);
            acc[j].w += __shfl_xor_sync(0xffffffffu, acc[j].w, 16);
        }
        const float inv = (s1 > s0) ? 1.f / ssum : 0.f;
        if (grp == 0) {
#pragma unroll
            for (int j = 0; j < VP4; j++) {
                sh[h][j * 32 + off0 + 0] = acc[j].x * inv;
                sh[h][j * 32 + off0 + 1] = acc[j].y * inv;
                sh[h][j * 32 + off0 + 2] = acc[j].z * inv;
                sh[h][j * 32 + off0 + 3] = acc[j].w * inv;
            }
        }
        __syncthreads();
        for (int d = threadIdx.x; d < D; d += blockDim.x) {
            float mx = fmaxf(fmaxf(sh[0][d], sh[1][d]), fmaxf(sh[2][d], sh[3][d]));
            if (SPLIT) {
                __nv_bfloat16 hi = __float2bfloat16_rn(mx);
                hh[(long)v * D + d] = hi;
                hl[(long)v * D + d] = __float2bfloat16_rn(mx - __bfloat162float(hi));
            } else {
                hout[(long)v * D + d] = mx;
            }
        }
        __syncthreads();
    }
}

// ---------------- global attention pooling: one block (128 thr) per graph ----------------
__global__ void k_pool(const float* __restrict__ gw, const float* __restrict__ gb,
                       float* __restrict__ out, int npg) {
    const int g = blockIdx.x;
    const int tid = threadIdx.x;
    const int lane = tid & 31;
    const int w = tid >> 5;
    extern __shared__ float sg[];
    __shared__ float red[16];
    const int base = g * npg;

    float gwr[4];
#pragma unroll
    for (int i = 0; i < 4; i++) gwr[i] = gw[i * 32 + lane];
    const float gbv = gb[0];

    for (int v = w; v < npg; v += 4) {
        const float* hp = g_h2 + (long)(base + v) * H2D;
        float p = 0.f;
#pragma unroll
        for (int i = 0; i < 4; i++) p += gwr[i] * hp[i * 32 + lane];
#pragma unroll
        for (int o = 16; o; o >>= 1) p += __shfl_xor_sync(0xffffffffu, p, o);
        if (lane == 0) sg[v] = p + gbv;
    }
    __syncthreads();

    float mx = -INF_;
    for (int v = tid; v < npg; v += 128) mx = fmaxf(mx, sg[v]);
#pragma unroll
    for (int o = 16; o; o >>= 1) mx = fmaxf(mx, __shfl_xor_sync(0xffffffffu, mx, o));
    if (lane == 0) red[w] = mx;
    __syncthreads();
    if (tid == 0) red[8] = fmaxf(fmaxf(red[0], red[1]), fmaxf(red[2], red[3]));
    __syncthreads();
    const float M = red[8];

    float ss = 0.f;
    for (int v = tid; v < npg; v += 128) {
        float e = __expf(sg[v] - M);
        sg[v] = e;
        ss += e;
    }
#pragma unroll
    for (int o = 16; o; o >>= 1) ss += __shfl_xor_sync(0xffffffffu, ss, o);
    if (lane == 0) red[w] = ss;
    __syncthreads();
    if (tid == 0) red[9] = red[0] + red[1] + red[2] + red[3];
    __syncthreads();
    const float inv = 1.f / red[9];

    float accD = 0.f;
    for (int v = 0; v < npg; v++)
        accD += sg[v] * g_h2[(long)(base + v) * H2D + tid];
    out[g * H2D + tid] = accD * inv;
}

// ---------------- launch ----------------
extern "C" void kernel_launch(void* const* d_in, const int* in_sizes, int n_in,
                              void* d_out, int out_size) {
    const float* x    = (const float*)d_in[0];
    const int* esrc   = (const int*)d_in[1];
    const int* edst   = (const int*)d_in[2];
    // d_in[3] = node_graph (contiguous blocks; unused)
    const float* Wl1  = (const float*)d_in[4];
    const float* bl1  = (const float*)d_in[5];
    const float* Wr1  = (const float*)d_in[6];
    const float* br1  = (const float*)d_in[7];
    const float* at1  = (const float*)d_in[8];
    const float* Wl2  = (const float*)d_in[9];
    const float* bl2  = (const float*)d_in[10];
    const float* Wr2  = (const float*)d_in[11];
    const float* br2  = (const float*)d_in[12];
    const float* at2  = (const float*)d_in[13];
    const float* gw   = (const float*)d_in[14];
    const float* gb   = (const float*)d_in[15];

    const int E = in_sizes[1];
    const int N = in_sizes[0] / 128;
    const int G = out_size / H2D;
    const int npg = N / G;

    float *fs1, *fd1, *fs2, *fd2, *h2;
    __nv_bfloat16 *xh, *xl, *h1h, *h1l;
    uint32_t* wb;
    int* degp;
    cudaGetSymbolAddress((void**)&fs1, g_fs1);
    cudaGetSymbolAddress((void**)&fd1, g_fd1);
    cudaGetSymbolAddress((void**)&fs2, g_fs2);
    cudaGetSymbolAddress((void**)&fd2, g_fd2);
    cudaGetSymbolAddress((void**)&h2,  g_h2);
    cudaGetSymbolAddress((void**)&xh,  g_xh);
    cudaGetSymbolAddress((void**)&xl,  g_xl);
    cudaGetSymbolAddress((void**)&h1h, g_h1h);
    cudaGetSymbolAddress((void**)&h1l, g_h1l);
    cudaGetSymbolAddress((void**)&wb,  g_wb);
    cudaGetSymbolAddress((void**)&degp, g_deg);

    const int rowBlocks = (N + 127) / 128;

    // ---- splits then gemm1: gemm1 is the 4th kernel launch -> ncu-profiled ----
    k_split_f32<<<(N * 128 + 255) / 256, 256>>>(x, xh, xl, N * 128);
    k_split_w<<<(64 * 256 + 255) / 256, 256>>>(Wl1, wb + 0 * 16384, wb + 1 * 16384, 64, 256);
    k_split_w<<<(64 * 256 + 255) / 256, 256>>>(Wr1, wb + 2 * 16384, wb + 3 * 16384, 64, 256);
    {
        dim3 grid(2 * (NH * H1D / 64), rowBlocks);
        k_gemm_bf16x3_dual<<<grid, 256>>>(xh, xl,
                                          wb + 0 * 16384, wb + 1 * 16384, bl1, fs1,
                                          wb + 2 * 16384, wb + 3 * 16384, br1, fd1,
                                          N, 128, NH * H1D);
    }

    // ---- CSR build (deterministic) ----
    cudaMemsetAsync(degp, 0, NN * sizeof(int));
    k_hist<<<(E + 255) / 256, 256>>>(edst, E);
    k_scan<<<1, 1024>>>(E);
    k_scatter<<<(E + 255) / 256, 256>>>(edst, E);
    k_sortseg_src<<<(NN + 3) / 4, 128>>>(esrc);

    // ---- GAT layer 1 -> split h1 ----
    k_gat<H1D, true><<<2368, 128>>>(fs1, fd1, at1, nullptr, h1h, h1l);

    // ---- layer 2 ----
    k_split_w<<<(32 * 512 + 255) / 256, 256>>>(Wl2, wb + 4 * 16384, wb + 5 * 16384, 32, 512);
    k_split_w<<<(32 * 512 + 255) / 256, 256>>>(Wr2, wb + 6 * 16384, wb + 7 * 16384, 32, 512);
    {
        dim3 grid(2 * (NH * H2D / 64), rowBlocks);
        k_gemm_bf16x3_dual<<<grid, 256>>>(h1h, h1l,
                                          wb + 4 * 16384, wb + 5 * 16384, bl2, fs2,
                                          wb + 6 * 16384, wb + 7 * 16384, br2, fd2,
                                          N, H1D, NH * H2D);
    }
    k_gat<H2D, false><<<2368, 128>>>(fs2, fd2, at2, h2, nullptr, nullptr);

    // ---- pooling ----
    k_pool<<<G, 128, npg * sizeof(float)>>>(gw, gb, (float*)d_out, npg);
}

// round 9
// speedup vs baseline: 1.6125x; 1.0275x over previous
#include <cuda_runtime.h>
#include <cuda_bf16.h>
#include <math.h>
#include <stdint.h>

// ---------------- problem constants (fixed by the dataset) ----------------
#define NN   50000      // nodes
#define EE   500000     // edges
#define GG   50         // graphs
#define NPG  1000       // nodes per graph
#define EPG  10000      // edges per graph
#define INF_ 3.402823466e+38f

#define H1D  64         // HID[0]
#define H2D  128        // HID[1]
#define NH   4          // heads
#define SLOPE 0.2f

// ---------------- scratch (device globals; no allocation) ----------------
__device__ float g_fs1[NN * NH * H1D];
__device__ float g_fd1[NN * NH * H1D];
__device__ float g_h1 [NN * H1D];
__device__ float g_fs2[NN * NH * H2D];
__device__ float g_fd2[NN * NH * H2D];
__device__ float g_h2 [NN * H2D];

__device__ int g_rs [NN + 1];
__device__ int g_adj[EE];       // dst-sorted src list (CSR payload)

// ---------------- fused CSR build: one block per graph ----------------
// Edges of graph g are exactly [g*EPG, (g+1)*EPG) with dst in [g*NPG, (g+1)*NPG).
// smem histogram -> smem scan -> smem-atomic scatter -> bitonic sort + src map.
__global__ __launch_bounds__(1024)
void k_csr(const int* __restrict__ esrc, const int* __restrict__ edst) {
    __shared__ int sdeg[1024];
    __shared__ int sexcl[1024];
    __shared__ int sscan[1024];
    __shared__ int scur[1024];
    const int g = blockIdx.x;
    const int tid = threadIdx.x;
    const int nbase = g * NPG, ebase = g * EPG;

    sdeg[tid] = 0;
    __syncthreads();
    for (int e = tid; e < EPG; e += 1024)
        atomicAdd(&sdeg[edst[ebase + e] - nbase], 1);
    __syncthreads();

    // inclusive scan over 1024 (Hillis-Steele)
    int val = sdeg[tid];
    sscan[tid] = val;
    __syncthreads();
    for (int off = 1; off < 1024; off <<= 1) {
        int t = (tid >= off) ? sscan[tid - off] : 0;
        __syncthreads();
        sscan[tid] += t;
        __syncthreads();
    }
    const int excl = sscan[tid] - val;
    sexcl[tid] = excl;
    scur[tid] = excl;
    if (tid < NPG) g_rs[nbase + tid] = ebase + excl;
    if (g == GG - 1 && tid == 0) g_rs[NN] = EE;
    __syncthreads();

    // scatter edge ids (order nondeterministic; sorted below for determinism)
    for (int e = tid; e < EPG; e += 1024) {
        int d = edst[ebase + e] - nbase;
        int p = atomicAdd(&scur[d], 1);
        g_adj[ebase + p] = ebase + e;
    }
    __syncthreads();

    // warp-per-node bitonic sort of edge ids, then map to src
    const int lane = tid & 31;
    const int w = tid >> 5;
    for (int v = w; v < NPG; v += 32) {
        const int d = sdeg[v];
        if (d <= 0) continue;
        const int s = ebase + sexcl[v];
        if (d <= 32) {
            int key = (lane < d) ? g_adj[s + lane] : 0x7FFFFFFF;
#pragma unroll
            for (int k = 2; k <= 32; k <<= 1) {
#pragma unroll
                for (int j = k >> 1; j > 0; j >>= 1) {
                    int o = __shfl_xor_sync(0xffffffffu, key, j);
                    bool up = ((lane & k) == 0);
                    bool low = ((lane & j) == 0);
                    int mn = min(key, o), mx = max(key, o);
                    key = (low == up) ? mn : mx;
                }
            }
            if (lane < d) g_adj[s + lane] = esrc[key];
        } else if (lane == 0) {
            for (int i = s + 1; i < s + d; i++) {
                int key = g_adj[i];
                int j = i - 1;
                while (j >= s && g_adj[j] > key) { g_adj[j + 1] = g_adj[j]; j--; }
                g_adj[j + 1] = key;
            }
            for (int i = s; i < s + d; i++) g_adj[i] = esrc[g_adj[i]];
        }
    }
}

// ---------------- bf16 split + mma helpers ----------------
__device__ __forceinline__ void split2(float x, float y, uint32_t& hi, uint32_t& lo) {
    __nv_bfloat16 hx = __float2bfloat16_rn(x);
    __nv_bfloat16 hy = __float2bfloat16_rn(y);
    hi = (uint32_t)__bfloat16_as_ushort(hx) | ((uint32_t)__bfloat16_as_ushort(hy) << 16);
    __nv_bfloat16 lx = __float2bfloat16_rn(x - __bfloat162float(hx));
    __nv_bfloat16 ly = __float2bfloat16_rn(y - __bfloat162float(hy));
    lo = (uint32_t)__bfloat16_as_ushort(lx) | ((uint32_t)__bfloat16_as_ushort(ly) << 16);
}

__device__ __forceinline__ void mma_bf16(float c[4], const uint32_t a[4], uint32_t b0, uint32_t b1) {
    asm("mma.sync.aligned.m16n8k16.row.col.f32.bf16.bf16.f32 "
        "{%0,%1,%2,%3}, {%4,%5,%6,%7}, {%8,%9}, {%0,%1,%2,%3};"
        : "+f"(c[0]), "+f"(c[1]), "+f"(c[2]), "+f"(c[3])
        : "r"(a[0]), "r"(a[1]), "r"(a[2]), "r"(a[3]), "r"(b0), "r"(b1));
}

// ---------------- fp32-in bf16x3 tensor GEMM + bias ----------------
// C[N,M] = A[N,K] @ B[K,M] + bias. A,B fp32; split to bf16 hi/lo in the tile
// loaders (3 mma passes: Ah*Bh + Al*Bh + Ah*Bl, ~1e-5 rel).
// Block tile 128x64, BK=32, 256 threads (8 warps: 4x2 of 32x32 warp tiles).
__global__ __launch_bounds__(256, 3)
void k_gemm_f32(const float* __restrict__ A, const float* __restrict__ B,
                const float* __restrict__ bias, float* __restrict__ C,
                int Nrows, int K, int M) {
    const int row0 = blockIdx.y << 7;
    const int col0 = blockIdx.x << 6;

    __shared__ uint32_t sA[2][128][20];    // [split][m][k2-word], pad 20
    __shared__ uint32_t sB[2][16][72];     // [split][k2-word][n], pad 72

    const int tid = threadIdx.x;
    const int lane = tid & 31;
    const int wid = tid >> 5;
    const int wm = wid & 3;
    const int wn = wid >> 2;
    const int g = lane >> 2;
    const int t = lane & 3;

    float acc[2][4][4];
#pragma unroll
    for (int i = 0; i < 2; i++)
#pragma unroll
        for (int j = 0; j < 4; j++)
#pragma unroll
            for (int q = 0; q < 4; q++) acc[i][j][q] = 0.f;

    const int ktiles = K >> 5;
    for (int kt = 0; kt < ktiles; kt++) {
        const int kk = kt << 5;
        // A tile: 128 rows x 32 fp32 = 1024 float4; 4 per thread; split in regs
#pragma unroll
        for (int i = 0; i < 4; i++) {
            int f = tid + i * 256;
            int r = f >> 3;                 // 8 float4 per row
            int c = (f & 7) * 4;            // float col
            float4 v = make_float4(0.f, 0.f, 0.f, 0.f);
            if (row0 + r < Nrows)
                v = *(const float4*)(A + (long)(row0 + r) * K + kk + c);
            uint32_t h0, l0, h1, l1;
            split2(v.x, v.y, h0, l0);
            split2(v.z, v.w, h1, l1);
            const int w0 = c >> 1;
            sA[0][r][w0] = h0; sA[0][r][w0 + 1] = h1;
            sA[1][r][w0] = l0; sA[1][r][w0 + 1] = l1;
        }
        // B tile: 32 k-rows x 64 fp32 -> words pairing k-rows (2k2, 2k2+1)
        {
            int k2 = tid >> 4;              // 0..15
            int n4 = (tid & 15) * 4;
            float4 a = *(const float4*)(B + (long)(kk + 2 * k2) * M + col0 + n4);
            float4 b = *(const float4*)(B + (long)(kk + 2 * k2 + 1) * M + col0 + n4);
            uint32_t h, l;
            split2(a.x, b.x, h, l); sB[0][k2][n4 + 0] = h; sB[1][k2][n4 + 0] = l;
            split2(a.y, b.y, h, l); sB[0][k2][n4 + 1] = h; sB[1][k2][n4 + 1] = l;
            split2(a.z, b.z, h, l); sB[0][k2][n4 + 2] = h; sB[1][k2][n4 + 2] = l;
            split2(a.w, b.w, h, l); sB[0][k2][n4 + 3] = h; sB[1][k2][n4 + 3] = l;
        }
        __syncthreads();

#pragma unroll
        for (int k16 = 0; k16 < 2; k16++) {
            const int kb = k16 * 8;
            uint32_t af[2][2][4];
#pragma unroll
            for (int s = 0; s < 2; s++)
#pragma unroll
                for (int mt = 0; mt < 2; mt++) {
                    const int mr = wm * 32 + mt * 16;
                    af[s][mt][0] = sA[s][mr + g][kb + t];
                    af[s][mt][1] = sA[s][mr + 8 + g][kb + t];
                    af[s][mt][2] = sA[s][mr + g][kb + 4 + t];
                    af[s][mt][3] = sA[s][mr + 8 + g][kb + 4 + t];
                }
#pragma unroll
            for (int nt = 0; nt < 4; nt++) {
                const int nc = wn * 32 + nt * 8 + g;
                uint32_t bh0 = sB[0][kb + t][nc];
                uint32_t bh1 = sB[0][kb + 4 + t][nc];
                uint32_t bl0 = sB[1][kb + t][nc];
                uint32_t bl1 = sB[1][kb + 4 + t][nc];
#pragma unroll
                for (int mt = 0; mt < 2; mt++) {
                    mma_bf16(acc[mt][nt], af[0][mt], bh0, bh1);
                    mma_bf16(acc[mt][nt], af[1][mt], bh0, bh1);
                    mma_bf16(acc[mt][nt], af[0][mt], bl0, bl1);
                }
            }
        }
        __syncthreads();
    }

#pragma unroll
    for (int nt = 0; nt < 4; nt++) {
        const int c = col0 + wn * 32 + nt * 8 + t * 2;
        const float2 bv = *(const float2*)(bias + c);
#pragma unroll
        for (int mt = 0; mt < 2; mt++) {
            const int r0 = row0 + wm * 32 + mt * 16 + g;
            if (r0 < Nrows) {
                float2 o; o.x = acc[mt][nt][0] + bv.x; o.y = acc[mt][nt][1] + bv.y;
                *(float2*)(C + (long)r0 * M + c) = o;
            }
            if (r0 + 8 < Nrows) {
                float2 o; o.x = acc[mt][nt][2] + bv.x; o.y = acc[mt][nt][3] + bv.y;
                *(float2*)(C + (long)(r0 + 8) * M + c) = o;
            }
        }
    }
}

// ---------------- batched fused GATv2 ----------------
// block = 128 thr = 4 warps = 4 heads. Warp splits into 32/GL groups of GL
// lanes; one edge per group per batch (D=64: GL=4 -> 8 edges/batch;
// D=128: GL=8 -> 4 edges/batch). float4 gathers; one softmax update per batch.
template <int D, int GL>
__global__ void k_gat(const float* __restrict__ fs, const float* __restrict__ fd,
                      const float* __restrict__ attn, float* __restrict__ hout) {
    constexpr int NG = 32 / GL;          // edges per batch
    constexpr int VP4 = D / (GL * 4);    // float4 chunks per lane
    constexpr int HD = NH * D;
    __shared__ float sh[NH][D];
    const int lane = threadIdx.x & 31;
    const int h = threadIdx.x >> 5;
    const int lg = lane & (GL - 1);
    const int grp = lane / GL;
    const int off0 = lg * 4;             // lane covers elems j*GL*4 + lg*4 ..+3

    float4 areg[VP4];
#pragma unroll
    for (int j = 0; j < VP4; j++)
        areg[j] = *(const float4*)(attn + h * D + j * GL * 4 + off0);

    for (int v = blockIdx.x; v < NN; v += gridDim.x) {
        float4 fdr[VP4];
        const float* fdp = fd + (long)v * HD + h * D;
#pragma unroll
        for (int j = 0; j < VP4; j++) fdr[j] = *(const float4*)(fdp + j * GL * 4 + off0);

        const int s0 = g_rs[v], s1 = g_rs[v + 1];
        float m = -INF_, ssum = 0.f;
        float4 acc[VP4];
#pragma unroll
        for (int j = 0; j < VP4; j++) acc[j] = make_float4(0.f, 0.f, 0.f, 0.f);

        for (int s = s0; s < s1; s += NG) {
            const int slot = s + grp;
            const bool valid = slot < s1;
            const int u = g_adj[valid ? slot : s0];
            const float* fsp = fs + (long)u * HD + h * D;
            float4 fu[VP4];
            float p = 0.f;
#pragma unroll
            for (int j = 0; j < VP4; j++) {
                fu[j] = *(const float4*)(fsp + j * GL * 4 + off0);
                float t0 = fu[j].x + fdr[j].x; t0 = t0 > 0.f ? t0 : SLOPE * t0;
                float t1 = fu[j].y + fdr[j].y; t1 = t1 > 0.f ? t1 : SLOPE * t1;
                float t2 = fu[j].z + fdr[j].z; t2 = t2 > 0.f ? t2 : SLOPE * t2;
                float t3 = fu[j].w + fdr[j].w; t3 = t3 > 0.f ? t3 : SLOPE * t3;
                p += areg[j].x * t0 + areg[j].y * t1 + areg[j].z * t2 + areg[j].w * t3;
            }
            // intra-group dot reduce -> all GL lanes hold the logit
#pragma unroll
            for (int o = 1; o < GL; o <<= 1) p += __shfl_xor_sync(0xffffffffu, p, o);
            if (!valid) p = -INF_;
            // batch max across groups
            float q = p;
#pragma unroll
            for (int o = GL; o < 32; o <<= 1) q = fmaxf(q, __shfl_xor_sync(0xffffffffu, q, o));
            // one online-softmax update per batch
            float mn = fmaxf(m, q);
            float sc = __expf(m - mn);       // first batch: exp(-inf) = 0
            float pe = __expf(p - mn);       // invalid edge: exp(-inf) = 0
            ssum = ssum * sc + pe;
#pragma unroll
            for (int j = 0; j < VP4; j++) {
                acc[j].x = acc[j].x * sc + pe * fu[j].x;
                acc[j].y = acc[j].y * sc + pe * fu[j].y;
                acc[j].z = acc[j].z * sc + pe * fu[j].z;
                acc[j].w = acc[j].w * sc + pe * fu[j].w;
            }
            m = mn;
        }
        // reduce partials across groups
#pragma unroll
        for (int o = GL; o < 32; o <<= 1) ssum += __shfl_xor_sync(0xffffffffu, ssum, o);
#pragma unroll
        for (int j = 0; j < VP4; j++) {
#pragma unroll
            for (int o = GL; o < 32; o <<= 1) {
                acc[j].x += __shfl_xor_sync(0xffffffffu, acc[j].x, o);
                acc[j].y += __shfl_xor_sync(0xffffffffu, acc[j].y, o);
                acc[j].z += __shfl_xor_sync(0xffffffffu, acc[j].z, o);
                acc[j].w += __shfl_xor_sync(0xffffffffu, acc[j].w, o);
            }
        }
        const float inv = (s1 > s0) ? 1.f / ssum : 0.f;
        if (grp == 0) {
#pragma unroll
            for (int j = 0; j < VP4; j++) {
                sh[h][j * GL * 4 + off0 + 0] = acc[j].x * inv;
                sh[h][j * GL * 4 + off0 + 1] = acc[j].y * inv;
                sh[h][j * GL * 4 + off0 + 2] = acc[j].z * inv;
                sh[h][j * GL * 4 + off0 + 3] = acc[j].w * inv;
            }
        }
        __syncthreads();
        for (int d = threadIdx.x; d < D; d += blockDim.x) {
            float mx = fmaxf(fmaxf(sh[0][d], sh[1][d]), fmaxf(sh[2][d], sh[3][d]));
            hout[(long)v * D + d] = mx;
        }
        __syncthreads();
    }
}

// ---------------- global attention pooling: one block (128 thr) per graph ----------------
__global__ void k_pool(const float* __restrict__ gw, const float* __restrict__ gb,
                       float* __restrict__ out, int npg) {
    const int g = blockIdx.x;
    const int tid = threadIdx.x;
    const int lane = tid & 31;
    const int w = tid >> 5;
    extern __shared__ float sg[];
    __shared__ float red[16];
    const int base = g * npg;

    float gwr[4];
#pragma unroll
    for (int i = 0; i < 4; i++) gwr[i] = gw[i * 32 + lane];
    const float gbv = gb[0];

    for (int v = w; v < npg; v += 4) {
        const float* hp = g_h2 + (long)(base + v) * H2D;
        float p = 0.f;
#pragma unroll
        for (int i = 0; i < 4; i++) p += gwr[i] * hp[i * 32 + lane];
#pragma unroll
        for (int o = 16; o; o >>= 1) p += __shfl_xor_sync(0xffffffffu, p, o);
        if (lane == 0) sg[v] = p + gbv;
    }
    __syncthreads();

    float mx = -INF_;
    for (int v = tid; v < npg; v += 128) mx = fmaxf(mx, sg[v]);
#pragma unroll
    for (int o = 16; o; o >>= 1) mx = fmaxf(mx, __shfl_xor_sync(0xffffffffu, mx, o));
    if (lane == 0) red[w] = mx;
    __syncthreads();
    if (tid == 0) red[8] = fmaxf(fmaxf(red[0], red[1]), fmaxf(red[2], red[3]));
    __syncthreads();
    const float M = red[8];

    float ss = 0.f;
    for (int v = tid; v < npg; v += 128) {
        float e = __expf(sg[v] - M);
        sg[v] = e;
        ss += e;
    }
#pragma unroll
    for (int o = 16; o; o >>= 1) ss += __shfl_xor_sync(0xffffffffu, ss, o);
    if (lane == 0) red[w] = ss;
    __syncthreads();
    if (tid == 0) red[9] = red[0] + red[1] + red[2] + red[3];
    __syncthreads();
    const float inv = 1.f / red[9];

    float accD = 0.f;
    for (int v = 0; v < npg; v++)
        accD += sg[v] * g_h2[(long)(base + v) * H2D + tid];
    out[g * H2D + tid] = accD * inv;
}

// ---------------- launch ----------------
extern "C" void kernel_launch(void* const* d_in, const int* in_sizes, int n_in,
                              void* d_out, int out_size) {
    const float* x    = (const float*)d_in[0];
    const int* esrc   = (const int*)d_in[1];
    const int* edst   = (const int*)d_in[2];
    // d_in[3] = node_graph (contiguous blocks; unused)
    const float* Wl1  = (const float*)d_in[4];
    const float* bl1  = (const float*)d_in[5];
    const float* Wr1  = (const float*)d_in[6];
    const float* br1  = (const float*)d_in[7];
    const float* at1  = (const float*)d_in[8];
    const float* Wl2  = (const float*)d_in[9];
    const float* bl2  = (const float*)d_in[10];
    const float* Wr2  = (const float*)d_in[11];
    const float* br2  = (const float*)d_in[12];
    const float* at2  = (const float*)d_in[13];
    const float* gw   = (const float*)d_in[14];
    const float* gb   = (const float*)d_in[15];

    const int N = in_sizes[0] / 128;
    const int G = out_size / H2D;
    const int npg = N / G;

    float *fs1, *fd1, *h1, *fs2, *fd2, *h2;
    cudaGetSymbolAddress((void**)&fs1, g_fs1);
    cudaGetSymbolAddress((void**)&fd1, g_fd1);
    cudaGetSymbolAddress((void**)&h1,  g_h1);
    cudaGetSymbolAddress((void**)&fs2, g_fs2);
    cudaGetSymbolAddress((void**)&fd2, g_fd2);
    cudaGetSymbolAddress((void**)&h2,  g_h2);

    const int rowBlocks = (N + 127) / 128;

    // 1: fused CSR build (deterministic via bitonic sort)
    k_csr<<<GG, 1024>>>(esrc, edst);

    // 2-3: layer-1 GEMMs (fp32 in, bf16x3 split in-kernel)
    k_gemm_f32<<<dim3(4, rowBlocks), 256>>>(x, Wl1, bl1, fs1, N, 128, NH * H1D);
    k_gemm_f32<<<dim3(4, rowBlocks), 256>>>(x, Wr1, br1, fd1, N, 128, NH * H1D);

    // 4: GAT layer 1 (D=64, 4-lane groups, 8 edges/batch)  <- ncu-profiled slot
    k_gat<H1D, 4><<<2368, 128>>>(fs1, fd1, at1, h1);

    // 5-6: layer-2 GEMMs
    k_gemm_f32<<<dim3(8, rowBlocks), 256>>>(h1, Wl2, bl2, fs2, N, H1D, NH * H2D);
    k_gemm_f32<<<dim3(8, rowBlocks), 256>>>(h1, Wr2, br2, fd2, N, H1D, NH * H2D);

    // 7: GAT layer 2 (D=128, 8-lane groups, 4 edges/batch)
    k_gat<H2D, 8><<<2368, 128>>>(fs2, fd2, at2, h2);

    // 8: pooling
    k_pool<<<G, 128, npg * sizeof(float)>>>(gw, gb, (float*)d_out, npg);
}

// round 10
// speedup vs baseline: 1.6380x; 1.0158x over previous
#include <cuda_runtime.h>
#include <cuda_bf16.h>
#include <math.h>
#include <stdint.h>

// ---------------- problem constants (fixed by the dataset) ----------------
#define NN   50000      // nodes
#define EE   500000     // edges
#define GG   50         // graphs
#define NPG  1000       // nodes per graph
#define EPG  10000      // edges per graph
#define INF_ 3.402823466e+38f

#define H1D  64         // HID[0]
#define H2D  128        // HID[1]
#define NH   4          // heads
#define SLOPE 0.2f

// ---------------- scratch (device globals; no allocation) ----------------
__device__ float g_fs1[NN * NH * H1D];
__device__ float g_fd1[NN * NH * H1D];
__device__ float g_h1 [NN * H1D];
__device__ float g_fs2[NN * NH * H2D];
__device__ float g_fd2[NN * NH * H2D];
__device__ float g_h2 [NN * H2D];

__device__ int g_rs [NN + 1];
__device__ int g_adj[EE];       // dst-sorted src list (CSR payload)

// ---------------- fused CSR build: one block per graph ----------------
__global__ __launch_bounds__(1024)
void k_csr(const int* __restrict__ esrc, const int* __restrict__ edst) {
    __shared__ int sdeg[1024];
    __shared__ int sexcl[1024];
    __shared__ int sscan[1024];
    __shared__ int scur[1024];
    const int g = blockIdx.x;
    const int tid = threadIdx.x;
    const int nbase = g * NPG, ebase = g * EPG;

    sdeg[tid] = 0;
    __syncthreads();
    for (int e = tid; e < EPG; e += 1024)
        atomicAdd(&sdeg[edst[ebase + e] - nbase], 1);
    __syncthreads();

    int val = sdeg[tid];
    sscan[tid] = val;
    __syncthreads();
    for (int off = 1; off < 1024; off <<= 1) {
        int t = (tid >= off) ? sscan[tid - off] : 0;
        __syncthreads();
        sscan[tid] += t;
        __syncthreads();
    }
    const int excl = sscan[tid] - val;
    sexcl[tid] = excl;
    scur[tid] = excl;
    if (tid < NPG) g_rs[nbase + tid] = ebase + excl;
    if (g == GG - 1 && tid == 0) g_rs[NN] = EE;
    __syncthreads();

    for (int e = tid; e < EPG; e += 1024) {
        int d = edst[ebase + e] - nbase;
        int p = atomicAdd(&scur[d], 1);
        g_adj[ebase + p] = ebase + e;
    }
    __syncthreads();

    const int lane = tid & 31;
    const int w = tid >> 5;
    for (int v = w; v < NPG; v += 32) {
        const int d = sdeg[v];
        if (d <= 0) continue;
        const int s = ebase + sexcl[v];
        if (d <= 32) {
            int key = (lane < d) ? g_adj[s + lane] : 0x7FFFFFFF;
#pragma unroll
            for (int k = 2; k <= 32; k <<= 1) {
#pragma unroll
                for (int j = k >> 1; j > 0; j >>= 1) {
                    int o = __shfl_xor_sync(0xffffffffu, key, j);
                    bool up = ((lane & k) == 0);
                    bool low = ((lane & j) == 0);
                    int mn = min(key, o), mx = max(key, o);
                    key = (low == up) ? mn : mx;
                }
            }
            if (lane < d) g_adj[s + lane] = esrc[key];
        } else if (lane == 0) {
            for (int i = s + 1; i < s + d; i++) {
                int key = g_adj[i];
                int j = i - 1;
                while (j >= s && g_adj[j] > key) { g_adj[j + 1] = g_adj[j]; j--; }
                g_adj[j + 1] = key;
            }
            for (int i = s; i < s + d; i++) g_adj[i] = esrc[g_adj[i]];
        }
    }
}

// ---------------- bf16 split + mma helpers ----------------
__device__ __forceinline__ void split2(float x, float y, uint32_t& hi, uint32_t& lo) {
    __nv_bfloat16 hx = __float2bfloat16_rn(x);
    __nv_bfloat16 hy = __float2bfloat16_rn(y);
    hi = (uint32_t)__bfloat16_as_ushort(hx) | ((uint32_t)__bfloat16_as_ushort(hy) << 16);
    __nv_bfloat16 lx = __float2bfloat16_rn(x - __bfloat162float(hx));
    __nv_bfloat16 ly = __float2bfloat16_rn(y - __bfloat162float(hy));
    lo = (uint32_t)__bfloat16_as_ushort(lx) | ((uint32_t)__bfloat16_as_ushort(ly) << 16);
}

__device__ __forceinline__ void mma_bf16(float c[4], const uint32_t a[4], uint32_t b0, uint32_t b1) {
    asm("mma.sync.aligned.m16n8k16.row.col.f32.bf16.bf16.f32 "
        "{%0,%1,%2,%3}, {%4,%5,%6,%7}, {%8,%9}, {%0,%1,%2,%3};"
        : "+f"(c[0]), "+f"(c[1]), "+f"(c[2]), "+f"(c[3])
        : "r"(a[0]), "r"(a[1]), "r"(a[2]), "r"(a[3]), "r"(b0), "r"(b1));
}

// ---------------- fp32-in bf16x3 tensor GEMM + bias ----------------
__global__ __launch_bounds__(256, 3)
void k_gemm_f32(const float* __restrict__ A, const float* __restrict__ B,
                const float* __restrict__ bias, float* __restrict__ C,
                int Nrows, int K, int M) {
    const int row0 = blockIdx.y << 7;
    const int col0 = blockIdx.x << 6;

    __shared__ uint32_t sA[2][128][20];
    __shared__ uint32_t sB[2][16][72];

    const int tid = threadIdx.x;
    const int lane = tid & 31;
    const int wid = tid >> 5;
    const int wm = wid & 3;
    const int wn = wid >> 2;
    const int g = lane >> 2;
    const int t = lane & 3;

    float acc[2][4][4];
#pragma unroll
    for (int i = 0; i < 2; i++)
#pragma unroll
        for (int j = 0; j < 4; j++)
#pragma unroll
            for (int q = 0; q < 4; q++) acc[i][j][q] = 0.f;

    const int ktiles = K >> 5;
    for (int kt = 0; kt < ktiles; kt++) {
        const int kk = kt << 5;
#pragma unroll
        for (int i = 0; i < 4; i++) {
            int f = tid + i * 256;
            int r = f >> 3;
            int c = (f & 7) * 4;
            float4 v = make_float4(0.f, 0.f, 0.f, 0.f);
            if (row0 + r < Nrows)
                v = *(const float4*)(A + (long)(row0 + r) * K + kk + c);
            uint32_t h0, l0, h1, l1;
            split2(v.x, v.y, h0, l0);
            split2(v.z, v.w, h1, l1);
            const int w0 = c >> 1;
            sA[0][r][w0] = h0; sA[0][r][w0 + 1] = h1;
            sA[1][r][w0] = l0; sA[1][r][w0 + 1] = l1;
        }
        {
            int k2 = tid >> 4;
            int n4 = (tid & 15) * 4;
            float4 a = *(const float4*)(B + (long)(kk + 2 * k2) * M + col0 + n4);
            float4 b = *(const float4*)(B + (long)(kk + 2 * k2 + 1) * M + col0 + n4);
            uint32_t h, l;
            split2(a.x, b.x, h, l); sB[0][k2][n4 + 0] = h; sB[1][k2][n4 + 0] = l;
            split2(a.y, b.y, h, l); sB[0][k2][n4 + 1] = h; sB[1][k2][n4 + 1] = l;
            split2(a.z, b.z, h, l); sB[0][k2][n4 + 2] = h; sB[1][k2][n4 + 2] = l;
            split2(a.w, b.w, h, l); sB[0][k2][n4 + 3] = h; sB[1][k2][n4 + 3] = l;
        }
        __syncthreads();

#pragma unroll
        for (int k16 = 0; k16 < 2; k16++) {
            const int kb = k16 * 8;
            uint32_t af[2][2][4];
#pragma unroll
            for (int s = 0; s < 2; s++)
#pragma unroll
                for (int mt = 0; mt < 2; mt++) {
                    const int mr = wm * 32 + mt * 16;
                    af[s][mt][0] = sA[s][mr + g][kb + t];
                    af[s][mt][1] = sA[s][mr + 8 + g][kb + t];
                    af[s][mt][2] = sA[s][mr + g][kb + 4 + t];
                    af[s][mt][3] = sA[s][mr + 8 + g][kb + 4 + t];
                }
#pragma unroll
            for (int nt = 0; nt < 4; nt++) {
                const int nc = wn * 32 + nt * 8 + g;
                uint32_t bh0 = sB[0][kb + t][nc];
                uint32_t bh1 = sB[0][kb + 4 + t][nc];
                uint32_t bl0 = sB[1][kb + t][nc];
                uint32_t bl1 = sB[1][kb + 4 + t][nc];
#pragma unroll
                for (int mt = 0; mt < 2; mt++) {
                    mma_bf16(acc[mt][nt], af[0][mt], bh0, bh1);
                    mma_bf16(acc[mt][nt], af[1][mt], bh0, bh1);
                    mma_bf16(acc[mt][nt], af[0][mt], bl0, bl1);
                }
            }
        }
        __syncthreads();
    }

#pragma unroll
    for (int nt = 0; nt < 4; nt++) {
        const int c = col0 + wn * 32 + nt * 8 + t * 2;
        const float2 bv = *(const float2*)(bias + c);
#pragma unroll
        for (int mt = 0; mt < 2; mt++) {
            const int r0 = row0 + wm * 32 + mt * 16 + g;
            if (r0 < Nrows) {
                float2 o; o.x = acc[mt][nt][0] + bv.x; o.y = acc[mt][nt][1] + bv.y;
                *(float2*)(C + (long)r0 * M + c) = o;
            }
            if (r0 + 8 < Nrows) {
                float2 o; o.x = acc[mt][nt][2] + bv.x; o.y = acc[mt][nt][3] + bv.y;
                *(float2*)(C + (long)(r0 + 8) * M + c) = o;
            }
        }
    }
}

// ---------------- batched fused GATv2, register-lean ----------------
// block = 128 thr = 4 warps = 4 heads. GL lanes per edge-group, NG=32/GL edges
// per online-softmax batch. ASMEM: attn vector read from shared (saves regs).
// MINB: occupancy floor via launch_bounds (GAT was RF-capped at 37.5% occ).
template <int D, int GL, bool ASMEM, int MINB>
__global__ __launch_bounds__(128, MINB)
void k_gat(const float* __restrict__ fs, const float* __restrict__ fd,
           const float* __restrict__ attn, float* __restrict__ hout) {
    constexpr int NG = 32 / GL;
    constexpr int VP4 = D / (GL * 4);
    constexpr int HD = NH * D;
    __shared__ float sh[NH][D];
    __shared__ float sattn[NH * D];
    const int lane = threadIdx.x & 31;
    const int h = threadIdx.x >> 5;
    const int lg = lane & (GL - 1);
    const int grp = lane / GL;
    const int off0 = lg * 4;

    float4 areg[ASMEM ? 1 : VP4];
    if (ASMEM) {
        for (int i = threadIdx.x * 4; i < NH * D; i += 512)
            *(float4*)&sattn[i] = *(const float4*)(attn + i);
        __syncthreads();
    } else {
#pragma unroll
        for (int j = 0; j < VP4; j++)
            areg[j] = *(const float4*)(attn + h * D + j * GL * 4 + off0);
    }

    for (int v = blockIdx.x; v < NN; v += gridDim.x) {
        float4 fdr[VP4];
        const float* fdp = fd + (long)v * HD + h * D;
#pragma unroll
        for (int j = 0; j < VP4; j++) fdr[j] = *(const float4*)(fdp + j * GL * 4 + off0);

        const int s0 = g_rs[v], s1 = g_rs[v + 1];
        float m = -INF_, ssum = 0.f;
        float4 acc[VP4];
#pragma unroll
        for (int j = 0; j < VP4; j++) acc[j] = make_float4(0.f, 0.f, 0.f, 0.f);

        for (int s = s0; s < s1; s += NG) {
            const int slot = s + grp;
            const bool valid = slot < s1;
            const int u = g_adj[valid ? slot : s0];
            const float* fsp = fs + (long)u * HD + h * D;
            float4 fu[VP4];
            float p = 0.f;
#pragma unroll
            for (int j = 0; j < VP4; j++) {
                fu[j] = *(const float4*)(fsp + j * GL * 4 + off0);
                float4 av = ASMEM ? *(const float4*)&sattn[h * D + j * GL * 4 + off0]
                                  : areg[j];
                float t0 = fu[j].x + fdr[j].x; t0 = fmaxf(t0, SLOPE * t0);
                float t1 = fu[j].y + fdr[j].y; t1 = fmaxf(t1, SLOPE * t1);
                float t2 = fu[j].z + fdr[j].z; t2 = fmaxf(t2, SLOPE * t2);
                float t3 = fu[j].w + fdr[j].w; t3 = fmaxf(t3, SLOPE * t3);
                p += av.x * t0 + av.y * t1 + av.z * t2 + av.w * t3;
            }
#pragma unroll
            for (int o = 1; o < GL; o <<= 1) p += __shfl_xor_sync(0xffffffffu, p, o);
            if (!valid) p = -INF_;
            float q = p;
#pragma unroll
            for (int o = GL; o < 32; o <<= 1) q = fmaxf(q, __shfl_xor_sync(0xffffffffu, q, o));
            float mn = fmaxf(m, q);
            float sc = __expf(m - mn);
            float pe = __expf(p - mn);
            ssum = ssum * sc + pe;
#pragma unroll
            for (int j = 0; j < VP4; j++) {
                acc[j].x = acc[j].x * sc + pe * fu[j].x;
                acc[j].y = acc[j].y * sc + pe * fu[j].y;
                acc[j].z = acc[j].z * sc + pe * fu[j].z;
                acc[j].w = acc[j].w * sc + pe * fu[j].w;
            }
            m = mn;
        }
#pragma unroll
        for (int o = GL; o < 32; o <<= 1) ssum += __shfl_xor_sync(0xffffffffu, ssum, o);
#pragma unroll
        for (int j = 0; j < VP4; j++) {
#pragma unroll
            for (int o = GL; o < 32; o <<= 1) {
                acc[j].x += __shfl_xor_sync(0xffffffffu, acc[j].x, o);
                acc[j].y += __shfl_xor_sync(0xffffffffu, acc[j].y, o);
                acc[j].z += __shfl_xor_sync(0xffffffffu, acc[j].z, o);
                acc[j].w += __shfl_xor_sync(0xffffffffu, acc[j].w, o);
            }
        }
        const float inv = (s1 > s0) ? 1.f / ssum : 0.f;
        if (grp == 0) {
#pragma unroll
            for (int j = 0; j < VP4; j++) {
                sh[h][j * GL * 4 + off0 + 0] = acc[j].x * inv;
                sh[h][j * GL * 4 + off0 + 1] = acc[j].y * inv;
                sh[h][j * GL * 4 + off0 + 2] = acc[j].z * inv;
                sh[h][j * GL * 4 + off0 + 3] = acc[j].w * inv;
            }
        }
        __syncthreads();
        for (int d = threadIdx.x; d < D; d += blockDim.x) {
            float mx = fmaxf(fmaxf(sh[0][d], sh[1][d]), fmaxf(sh[2][d], sh[3][d]));
            hout[(long)v * D + d] = mx;
        }
        __syncthreads();
    }
}

// ---------------- global attention pooling: one block (128 thr) per graph ----------------
__global__ void k_pool(const float* __restrict__ gw, const float* __restrict__ gb,
                       float* __restrict__ out, int npg) {
    const int g = blockIdx.x;
    const int tid = threadIdx.x;
    const int lane = tid & 31;
    const int w = tid >> 5;
    extern __shared__ float sg[];
    __shared__ float red[16];
    const int base = g * npg;

    float gwr[4];
#pragma unroll
    for (int i = 0; i < 4; i++) gwr[i] = gw[i * 32 + lane];
    const float gbv = gb[0];

    for (int v = w; v < npg; v += 4) {
        const float* hp = g_h2 + (long)(base + v) * H2D;
        float p = 0.f;
#pragma unroll
        for (int i = 0; i < 4; i++) p += gwr[i] * hp[i * 32 + lane];
#pragma unroll
        for (int o = 16; o; o >>= 1) p += __shfl_xor_sync(0xffffffffu, p, o);
        if (lane == 0) sg[v] = p + gbv;
    }
    __syncthreads();

    float mx = -INF_;
    for (int v = tid; v < npg; v += 128) mx = fmaxf(mx, sg[v]);
#pragma unroll
    for (int o = 16; o; o >>= 1) mx = fmaxf(mx, __shfl_xor_sync(0xffffffffu, mx, o));
    if (lane == 0) red[w] = mx;
    __syncthreads();
    if (tid == 0) red[8] = fmaxf(fmaxf(red[0], red[1]), fmaxf(red[2], red[3]));
    __syncthreads();
    const float M = red[8];

    float ss = 0.f;
    for (int v = tid; v < npg; v += 128) {
        float e = __expf(sg[v] - M);
        sg[v] = e;
        ss += e;
    }
#pragma unroll
    for (int o = 16; o; o >>= 1) ss += __shfl_xor_sync(0xffffffffu, ss, o);
    if (lane == 0) red[w] = ss;
    __syncthreads();
    if (tid == 0) red[9] = red[0] + red[1] + red[2] + red[3];
    __syncthreads();
    const float inv = 1.f / red[9];

    float accD = 0.f;
    for (int v = 0; v < npg; v++)
        accD += sg[v] * g_h2[(long)(base + v) * H2D + tid];
    out[g * H2D + tid] = accD * inv;
}

// ---------------- launch ----------------
extern "C" void kernel_launch(void* const* d_in, const int* in_sizes, int n_in,
                              void* d_out, int out_size) {
    const float* x    = (const float*)d_in[0];
    const int* esrc   = (const int*)d_in[1];
    const int* edst   = (const int*)d_in[2];
    // d_in[3] = node_graph (contiguous blocks; unused)
    const float* Wl1  = (const float*)d_in[4];
    const float* bl1  = (const float*)d_in[5];
    const float* Wr1  = (const float*)d_in[6];
    const float* br1  = (const float*)d_in[7];
    const float* at1  = (const float*)d_in[8];
    const float* Wl2  = (const float*)d_in[9];
    const float* bl2  = (const float*)d_in[10];
    const float* Wr2  = (const float*)d_in[11];
    const float* br2  = (const float*)d_in[12];
    const float* at2  = (const float*)d_in[13];
    const float* gw   = (const float*)d_in[14];
    const float* gb   = (const float*)d_in[15];

    const int N = in_sizes[0] / 128;
    const int G = out_size / H2D;
    const int npg = N / G;

    float *fs1, *fd1, *h1, *fs2, *fd2, *h2;
    cudaGetSymbolAddress((void**)&fs1, g_fs1);
    cudaGetSymbolAddress((void**)&fd1, g_fd1);
    cudaGetSymbolAddress((void**)&h1,  g_h1);
    cudaGetSymbolAddress((void**)&fs2, g_fs2);
    cudaGetSymbolAddress((void**)&fd2, g_fd2);
    cudaGetSymbolAddress((void**)&h2,  g_h2);

    const int rowBlocks = (N + 127) / 128;

    // 1: fused CSR build (deterministic via bitonic sort)
    k_csr<<<GG, 1024>>>(esrc, edst);

    // 2-3: layer-1 GEMMs
    k_gemm_f32<<<dim3(4, rowBlocks), 256>>>(x, Wl1, bl1, fs1, N, 128, NH * H1D);
    k_gemm_f32<<<dim3(4, rowBlocks), 256>>>(x, Wr1, br1, fd1, N, 128, NH * H1D);

    // 4: GAT layer 1 (GL=8, reg-lean, occ floor 10 blocks/SM)  <- profiled slot
    k_gat<H1D, 8, false, 10><<<2368, 128>>>(fs1, fd1, at1, h1);

    // 5-6: layer-2 GEMMs
    k_gemm_f32<<<dim3(8, rowBlocks), 256>>>(h1, Wl2, bl2, fs2, N, H1D, NH * H2D);
    k_gemm_f32<<<dim3(8, rowBlocks), 256>>>(h1, Wr2, br2, fd2, N, H1D, NH * H2D);

    // 7: GAT layer 2 (GL=8, attn in smem, occ floor 8 blocks/SM)
    k_gat<H2D, 8, true, 8><<<2368, 128>>>(fs2, fd2, at2, h2);

    // 8: pooling
    k_pool<<<G, 128, npg * sizeof(float)>>>(gw, gb, (float*)d_out, npg);
}

// round 11
// speedup vs baseline: 1.7940x; 1.0953x over previous
#include <cuda_runtime.h>
#include <cuda_bf16.h>
#include <math.h>
#include <stdint.h>

// ---------------- problem constants (fixed by the dataset) ----------------
#define NN   50000      // nodes
#define EE   500000     // edges
#define GG   50         // graphs
#define NPG  1000       // nodes per graph
#define EPG  10000      // edges per graph
#define INF_ 3.402823466e+38f

#define H1D  64         // HID[0]
#define H2D  128        // HID[1]
#define NH   4          // heads
#define SLOPE 0.2f

// ---------------- scratch (device globals; no allocation) ----------------
__device__ float g_fs1[NN * NH * H1D];
__device__ float g_fd1[NN * NH * H1D];
__device__ float g_h1 [NN * H1D];
__device__ float g_fs2[NN * NH * H2D];
__device__ float g_fd2[NN * NH * H2D];
__device__ float g_h2 [NN * H2D];

__device__ int g_rs [NN + 1];
__device__ int g_adj[EE];       // dst-sorted src list (CSR payload)

// ---------------- fused CSR build: one block per graph ----------------
__global__ __launch_bounds__(1024)
void k_csr(const int* __restrict__ esrc, const int* __restrict__ edst) {
    __shared__ int sdeg[1024];
    __shared__ int sexcl[1024];
    __shared__ int sscan[1024];
    __shared__ int scur[1024];
    const int g = blockIdx.x;
    const int tid = threadIdx.x;
    const int nbase = g * NPG, ebase = g * EPG;

    sdeg[tid] = 0;
    __syncthreads();
    for (int e = tid; e < EPG; e += 1024)
        atomicAdd(&sdeg[edst[ebase + e] - nbase], 1);
    __syncthreads();

    int val = sdeg[tid];
    sscan[tid] = val;
    __syncthreads();
    for (int off = 1; off < 1024; off <<= 1) {
        int t = (tid >= off) ? sscan[tid - off] : 0;
        __syncthreads();
        sscan[tid] += t;
        __syncthreads();
    }
    const int excl = sscan[tid] - val;
    sexcl[tid] = excl;
    scur[tid] = excl;
    if (tid < NPG) g_rs[nbase + tid] = ebase + excl;
    if (g == GG - 1 && tid == 0) g_rs[NN] = EE;
    __syncthreads();

    for (int e = tid; e < EPG; e += 1024) {
        int d = edst[ebase + e] - nbase;
        int p = atomicAdd(&scur[d], 1);
        g_adj[ebase + p] = ebase + e;
    }
    __syncthreads();

    const int lane = tid & 31;
    const int w = tid >> 5;
    for (int v = w; v < NPG; v += 32) {
        const int d = sdeg[v];
        if (d <= 0) continue;
        const int s = ebase + sexcl[v];
        if (d <= 32) {
            int key = (lane < d) ? g_adj[s + lane] : 0x7FFFFFFF;
#pragma unroll
            for (int k = 2; k <= 32; k <<= 1) {
#pragma unroll
                for (int j = k >> 1; j > 0; j >>= 1) {
                    int o = __shfl_xor_sync(0xffffffffu, key, j);
                    bool up = ((lane & k) == 0);
                    bool low = ((lane & j) == 0);
                    int mn = min(key, o), mx = max(key, o);
                    key = (low == up) ? mn : mx;
                }
            }
            if (lane < d) g_adj[s + lane] = esrc[key];
        } else if (lane == 0) {
            for (int i = s + 1; i < s + d; i++) {
                int key = g_adj[i];
                int j = i - 1;
                while (j >= s && g_adj[j] > key) { g_adj[j + 1] = g_adj[j]; j--; }
                g_adj[j + 1] = key;
            }
            for (int i = s; i < s + d; i++) g_adj[i] = esrc[g_adj[i]];
        }
    }
}

// ---------------- bf16 split + mma helpers ----------------
__device__ __forceinline__ void split2(float x, float y, uint32_t& hi, uint32_t& lo) {
    __nv_bfloat16 hx = __float2bfloat16_rn(x);
    __nv_bfloat16 hy = __float2bfloat16_rn(y);
    hi = (uint32_t)__bfloat16_as_ushort(hx) | ((uint32_t)__bfloat16_as_ushort(hy) << 16);
    __nv_bfloat16 lx = __float2bfloat16_rn(x - __bfloat162float(hx));
    __nv_bfloat16 ly = __float2bfloat16_rn(y - __bfloat162float(hy));
    lo = (uint32_t)__bfloat16_as_ushort(lx) | ((uint32_t)__bfloat16_as_ushort(ly) << 16);
}

__device__ __forceinline__ void mma_bf16(float c[4], const uint32_t a[4], uint32_t b0, uint32_t b1) {
    asm("mma.sync.aligned.m16n8k16.row.col.f32.bf16.bf16.f32 "
        "{%0,%1,%2,%3}, {%4,%5,%6,%7}, {%8,%9}, {%0,%1,%2,%3};"
        : "+f"(c[0]), "+f"(c[1]), "+f"(c[2]), "+f"(c[3])
        : "r"(a[0]), "r"(a[1]), "r"(a[2]), "r"(a[3]), "r"(b0), "r"(b1));
}

// ---------------- fp32-in dual-output bf16x3 tensor GEMM + bias ----------------
// grid.x = 2*(M/64): first half computes C1 = A@B1+b1, second half C2 = A@B2+b2.
// Block tile 128x64, BK=32, 256 threads; bf16 hi/lo split in the tile loaders.
__global__ __launch_bounds__(256, 3)
void k_gemm_f32_dual(const float* __restrict__ A,
                     const float* __restrict__ B1, const float* __restrict__ b1, float* __restrict__ C1,
                     const float* __restrict__ B2, const float* __restrict__ b2, float* __restrict__ C2,
                     int Nrows, int K, int M) {
    const int nbx = M >> 6;
    int bx = blockIdx.x;
    const float* B = B1; const float* bias = b1; float* C = C1;
    if (bx >= nbx) { bx -= nbx; B = B2; bias = b2; C = C2; }
    const int row0 = blockIdx.y << 7;
    const int col0 = bx << 6;

    __shared__ uint32_t sA[2][128][20];
    __shared__ uint32_t sB[2][16][72];

    const int tid = threadIdx.x;
    const int lane = tid & 31;
    const int wid = tid >> 5;
    const int wm = wid & 3;
    const int wn = wid >> 2;
    const int g = lane >> 2;
    const int t = lane & 3;

    float acc[2][4][4];
#pragma unroll
    for (int i = 0; i < 2; i++)
#pragma unroll
        for (int j = 0; j < 4; j++)
#pragma unroll
            for (int q = 0; q < 4; q++) acc[i][j][q] = 0.f;

    const int ktiles = K >> 5;
    for (int kt = 0; kt < ktiles; kt++) {
        const int kk = kt << 5;
#pragma unroll
        for (int i = 0; i < 4; i++) {
            int f = tid + i * 256;
            int r = f >> 3;
            int c = (f & 7) * 4;
            float4 v = make_float4(0.f, 0.f, 0.f, 0.f);
            if (row0 + r < Nrows)
                v = *(const float4*)(A + (long)(row0 + r) * K + kk + c);
            uint32_t h0, l0, h1, l1;
            split2(v.x, v.y, h0, l0);
            split2(v.z, v.w, h1, l1);
            const int w0 = c >> 1;
            sA[0][r][w0] = h0; sA[0][r][w0 + 1] = h1;
            sA[1][r][w0] = l0; sA[1][r][w0 + 1] = l1;
        }
        {
            int k2 = tid >> 4;
            int n4 = (tid & 15) * 4;
            float4 a = *(const float4*)(B + (long)(kk + 2 * k2) * M + col0 + n4);
            float4 b = *(const float4*)(B + (long)(kk + 2 * k2 + 1) * M + col0 + n4);
            uint32_t h, l;
            split2(a.x, b.x, h, l); sB[0][k2][n4 + 0] = h; sB[1][k2][n4 + 0] = l;
            split2(a.y, b.y, h, l); sB[0][k2][n4 + 1] = h; sB[1][k2][n4 + 1] = l;
            split2(a.z, b.z, h, l); sB[0][k2][n4 + 2] = h; sB[1][k2][n4 + 2] = l;
            split2(a.w, b.w, h, l); sB[0][k2][n4 + 3] = h; sB[1][k2][n4 + 3] = l;
        }
        __syncthreads();

#pragma unroll
        for (int k16 = 0; k16 < 2; k16++) {
            const int kb = k16 * 8;
            uint32_t af[2][2][4];
#pragma unroll
            for (int s = 0; s < 2; s++)
#pragma unroll
                for (int mt = 0; mt < 2; mt++) {
                    const int mr = wm * 32 + mt * 16;
                    af[s][mt][0] = sA[s][mr + g][kb + t];
                    af[s][mt][1] = sA[s][mr + 8 + g][kb + t];
                    af[s][mt][2] = sA[s][mr + g][kb + 4 + t];
                    af[s][mt][3] = sA[s][mr + 8 + g][kb + 4 + t];
                }
#pragma unroll
            for (int nt = 0; nt < 4; nt++) {
                const int nc = wn * 32 + nt * 8 + g;
                uint32_t bh0 = sB[0][kb + t][nc];
                uint32_t bh1 = sB[0][kb + 4 + t][nc];
                uint32_t bl0 = sB[1][kb + t][nc];
                uint32_t bl1 = sB[1][kb + 4 + t][nc];
#pragma unroll
                for (int mt = 0; mt < 2; mt++) {
                    mma_bf16(acc[mt][nt], af[0][mt], bh0, bh1);
                    mma_bf16(acc[mt][nt], af[1][mt], bh0, bh1);
                    mma_bf16(acc[mt][nt], af[0][mt], bl0, bl1);
                }
            }
        }
        __syncthreads();
    }

#pragma unroll
    for (int nt = 0; nt < 4; nt++) {
        const int c = col0 + wn * 32 + nt * 8 + t * 2;
        const float2 bv = *(const float2*)(bias + c);
#pragma unroll
        for (int mt = 0; mt < 2; mt++) {
            const int r0 = row0 + wm * 32 + mt * 16 + g;
            if (r0 < Nrows) {
                float2 o; o.x = acc[mt][nt][0] + bv.x; o.y = acc[mt][nt][1] + bv.y;
                *(float2*)(C + (long)r0 * M + c) = o;
            }
            if (r0 + 8 < Nrows) {
                float2 o; o.x = acc[mt][nt][2] + bv.x; o.y = acc[mt][nt][3] + bv.y;
                *(float2*)(C + (long)(r0 + 8) * M + c) = o;
            }
        }
    }
}

// ---------------- batched fused GATv2, register-lean ----------------
// block = 128 thr = 4 warps = 4 heads. GL lanes per edge-group, NG=32/GL edges
// per online-softmax batch. VP4 = D/(GL*4) float4 chunks per lane.
// D=64: GL=8 -> VP4=2, regs~48 (measured).  D=128: GL=16 -> VP4=2, same shape.
template <int D, int GL, int MINB>
__global__ __launch_bounds__(128, MINB)
void k_gat(const float* __restrict__ fs, const float* __restrict__ fd,
           const float* __restrict__ attn, float* __restrict__ hout) {
    constexpr int NG = 32 / GL;
    constexpr int VP4 = D / (GL * 4);
    constexpr int HD = NH * D;
    __shared__ float sh[NH][D];
    const int lane = threadIdx.x & 31;
    const int h = threadIdx.x >> 5;
    const int lg = lane & (GL - 1);
    const int grp = lane / GL;
    const int off0 = lg * 4;

    float4 areg[VP4];
#pragma unroll
    for (int j = 0; j < VP4; j++)
        areg[j] = *(const float4*)(attn + h * D + j * GL * 4 + off0);

    for (int v = blockIdx.x; v < NN; v += gridDim.x) {
        float4 fdr[VP4];
        const float* fdp = fd + (long)v * HD + h * D;
#pragma unroll
        for (int j = 0; j < VP4; j++) fdr[j] = *(const float4*)(fdp + j * GL * 4 + off0);

        const int s0 = g_rs[v], s1 = g_rs[v + 1];
        float m = -INF_, ssum = 0.f;
        float4 acc[VP4];
#pragma unroll
        for (int j = 0; j < VP4; j++) acc[j] = make_float4(0.f, 0.f, 0.f, 0.f);

        for (int s = s0; s < s1; s += NG) {
            const int slot = s + grp;
            const bool valid = slot < s1;
            const int u = g_adj[valid ? slot : s0];
            const float* fsp = fs + (long)u * HD + h * D;
            float4 fu[VP4];
            float p = 0.f;
#pragma unroll
            for (int j = 0; j < VP4; j++) {
                fu[j] = *(const float4*)(fsp + j * GL * 4 + off0);
                float t0 = fu[j].x + fdr[j].x; t0 = fmaxf(t0, SLOPE * t0);
                float t1 = fu[j].y + fdr[j].y; t1 = fmaxf(t1, SLOPE * t1);
                float t2 = fu[j].z + fdr[j].z; t2 = fmaxf(t2, SLOPE * t2);
                float t3 = fu[j].w + fdr[j].w; t3 = fmaxf(t3, SLOPE * t3);
                p += areg[j].x * t0 + areg[j].y * t1 + areg[j].z * t2 + areg[j].w * t3;
            }
#pragma unroll
            for (int o = 1; o < GL; o <<= 1) p += __shfl_xor_sync(0xffffffffu, p, o);
            if (!valid) p = -INF_;
            float q = p;
#pragma unroll
            for (int o = GL; o < 32; o <<= 1) q = fmaxf(q, __shfl_xor_sync(0xffffffffu, q, o));
            float mn = fmaxf(m, q);
            float sc = __expf(m - mn);       // first batch: exp(-inf) = 0
            float pe = __expf(p - mn);       // invalid edge: exp(-inf) = 0
            ssum = ssum * sc + pe;
#pragma unroll
            for (int j = 0; j < VP4; j++) {
                acc[j].x = acc[j].x * sc + pe * fu[j].x;
                acc[j].y = acc[j].y * sc + pe * fu[j].y;
                acc[j].z = acc[j].z * sc + pe * fu[j].z;
                acc[j].w = acc[j].w * sc + pe * fu[j].w;
            }
            m = mn;
        }
#pragma unroll
        for (int o = GL; o < 32; o <<= 1) ssum += __shfl_xor_sync(0xffffffffu, ssum, o);
#pragma unroll
        for (int j = 0; j < VP4; j++) {
#pragma unroll
            for (int o = GL; o < 32; o <<= 1) {
                acc[j].x += __shfl_xor_sync(0xffffffffu, acc[j].x, o);
                acc[j].y += __shfl_xor_sync(0xffffffffu, acc[j].y, o);
                acc[j].z += __shfl_xor_sync(0xffffffffu, acc[j].z, o);
                acc[j].w += __shfl_xor_sync(0xffffffffu, acc[j].w, o);
            }
        }
        const float inv = (s1 > s0) ? 1.f / ssum : 0.f;
        if (grp == 0) {
#pragma unroll
            for (int j = 0; j < VP4; j++) {
                sh[h][j * GL * 4 + off0 + 0] = acc[j].x * inv;
                sh[h][j * GL * 4 + off0 + 1] = acc[j].y * inv;
                sh[h][j * GL * 4 + off0 + 2] = acc[j].z * inv;
                sh[h][j * GL * 4 + off0 + 3] = acc[j].w * inv;
            }
        }
        __syncthreads();
        for (int d = threadIdx.x; d < D; d += blockDim.x) {
            float mx = fmaxf(fmaxf(sh[0][d], sh[1][d]), fmaxf(sh[2][d], sh[3][d]));
            hout[(long)v * D + d] = mx;
        }
        __syncthreads();
    }
}

// ---------------- global attention pooling: one block (128 thr) per graph ----------------
__global__ void k_pool(const float* __restrict__ gw, const float* __restrict__ gb,
                       float* __restrict__ out, int npg) {
    const int g = blockIdx.x;
    const int tid = threadIdx.x;
    const int lane = tid & 31;
    const int w = tid >> 5;
    extern __shared__ float sg[];
    __shared__ float red[16];
    const int base = g * npg;

    float gwr[4];
#pragma unroll
    for (int i = 0; i < 4; i++) gwr[i] = gw[i * 32 + lane];
    const float gbv = gb[0];

    for (int v = w; v < npg; v += 4) {
        const float* hp = g_h2 + (long)(base + v) * H2D;
        float p = 0.f;
#pragma unroll
        for (int i = 0; i < 4; i++) p += gwr[i] * hp[i * 32 + lane];
#pragma unroll
        for (int o = 16; o; o >>= 1) p += __shfl_xor_sync(0xffffffffu, p, o);
        if (lane == 0) sg[v] = p + gbv;
    }
    __syncthreads();

    float mx = -INF_;
    for (int v = tid; v < npg; v += 128) mx = fmaxf(mx, sg[v]);
#pragma unroll
    for (int o = 16; o; o >>= 1) mx = fmaxf(mx, __shfl_xor_sync(0xffffffffu, mx, o));
    if (lane == 0) red[w] = mx;
    __syncthreads();
    if (tid == 0) red[8] = fmaxf(fmaxf(red[0], red[1]), fmaxf(red[2], red[3]));
    __syncthreads();
    const float M = red[8];

    float ss = 0.f;
    for (int v = tid; v < npg; v += 128) {
        float e = __expf(sg[v] - M);
        sg[v] = e;
        ss += e;
    }
#pragma unroll
    for (int o = 16; o; o >>= 1) ss += __shfl_xor_sync(0xffffffffu, ss, o);
    if (lane == 0) red[w] = ss;
    __syncthreads();
    if (tid == 0) red[9] = red[0] + red[1] + red[2] + red[3];
    __syncthreads();
    const float inv = 1.f / red[9];

    float accD = 0.f;
    for (int v = 0; v < npg; v++)
        accD += sg[v] * g_h2[(long)(base + v) * H2D + tid];
    out[g * H2D + tid] = accD * inv;
}

// ---------------- launch ----------------
extern "C" void kernel_launch(void* const* d_in, const int* in_sizes, int n_in,
                              void* d_out, int out_size) {
    const float* x    = (const float*)d_in[0];
    const int* esrc   = (const int*)d_in[1];
    const int* edst   = (const int*)d_in[2];
    // d_in[3] = node_graph (contiguous blocks; unused)
    const float* Wl1  = (const float*)d_in[4];
    const float* bl1  = (const float*)d_in[5];
    const float* Wr1  = (const float*)d_in[6];
    const float* br1  = (const float*)d_in[7];
    const float* at1  = (const float*)d_in[8];
    const float* Wl2  = (const float*)d_in[9];
    const float* bl2  = (const float*)d_in[10];
    const float* Wr2  = (const float*)d_in[11];
    const float* br2  = (const float*)d_in[12];
    const float* at2  = (const float*)d_in[13];
    const float* gw   = (const float*)d_in[14];
    const float* gb   = (const float*)d_in[15];

    const int N = in_sizes[0] / 128;
    const int G = out_size / H2D;
    const int npg = N / G;

    float *fs1, *fd1, *h1, *fs2, *fd2, *h2;
    cudaGetSymbolAddress((void**)&fs1, g_fs1);
    cudaGetSymbolAddress((void**)&fd1, g_fd1);
    cudaGetSymbolAddress((void**)&h1,  g_h1);
    cudaGetSymbolAddress((void**)&fs2, g_fs2);
    cudaGetSymbolAddress((void**)&fd2, g_fd2);
    cudaGetSymbolAddress((void**)&h2,  g_h2);

    const int rowBlocks = (N + 127) / 128;

    // 1: layer-1 dual GEMM (fs1 + fd1 in one launch)
    k_gemm_f32_dual<<<dim3(8, rowBlocks), 256>>>(x, Wl1, bl1, fs1, Wr1, br1, fd1,
                                                 N, 128, NH * H1D);
    // 2: fused CSR build (deterministic via bitonic sort)
    k_csr<<<GG, 1024>>>(esrc, edst);

    // 3: GAT layer 1 (GL=8, regs 48, measured 120us)
    k_gat<H1D, 8, 10><<<2368, 128>>>(fs1, fd1, at1, h1);

    // 4: layer-2 dual GEMM  <- ncu-profiled slot
    k_gemm_f32_dual<<<dim3(16, rowBlocks), 256>>>(h1, Wl2, bl2, fs2, Wr2, br2, fd2,
                                                  N, H1D, NH * H2D);

    // 5: GAT layer 2 (GL=16 -> VP4=2, same reg shape as GAT1; no spills)
    k_gat<H2D, 16, 10><<<2368, 128>>>(fs2, fd2, at2, h2);

    // 6: pooling
    k_pool<<<G, 128, npg * sizeof(float)>>>(gw, gb, (float*)d_out, npg);
}